// round 1
// baseline (speedup 1.0000x reference)
#include <cuda_runtime.h>
#include <cstdint>

#define N_NODES 20000
#define N_EDGES 320000
#define DK      256
#define M_PAD   20096   // 157 * 128
#define BN_EPS  1e-5f

// ---------------- static scratch (no allocation allowed) ----------------
__device__ float g_h[M_PAD * DK];
__device__ float g_z[M_PAD * DK];
__device__ float g_t[M_PAD * DK];
__device__ int   g_deg[N_NODES];
__device__ int   g_offs[N_NODES + 1];
__device__ int   g_cursor[N_NODES];
__device__ int   g_csrc[N_EDGES];

// ---------------- CSR build ----------------
__global__ void count_kernel(const int* __restrict__ dst) {
    int e = blockIdx.x * blockDim.x + threadIdx.x;
    if (e < N_EDGES) atomicAdd(&g_deg[dst[e]], 1);
}

__global__ void scan_kernel() {
    __shared__ int carry;
    __shared__ int wsum[32];
    int tid = threadIdx.x, lane = tid & 31, wid = tid >> 5;
    if (tid == 0) carry = 0;
    __syncthreads();
    for (int base = 0; base < N_NODES; base += 1024) {
        int i = base + tid;
        int v = (i < N_NODES) ? g_deg[i] : 0;
        int s = v;
        #pragma unroll
        for (int d = 1; d < 32; d <<= 1) {
            int t = __shfl_up_sync(0xffffffffu, s, d);
            if (lane >= d) s += t;
        }
        if (lane == 31) wsum[wid] = s;
        __syncthreads();
        if (wid == 0) {
            int ws = wsum[lane];
            #pragma unroll
            for (int d = 1; d < 32; d <<= 1) {
                int t = __shfl_up_sync(0xffffffffu, ws, d);
                if (lane >= d) ws += t;
            }
            wsum[lane] = ws;
        }
        __syncthreads();
        int excl = s - v + (wid > 0 ? wsum[wid - 1] : 0) + carry;
        if (i < N_NODES) g_offs[i] = excl;
        int total = wsum[31];
        __syncthreads();
        if (tid == 0) carry += total;
        __syncthreads();
    }
    if (tid == 0) g_offs[N_NODES] = carry;
}

__global__ void fill_kernel(const int* __restrict__ src, const int* __restrict__ dst) {
    int e = blockIdx.x * blockDim.x + threadIdx.x;
    if (e < N_EDGES) {
        int d = dst[e];
        int pos = atomicAdd(&g_cursor[d], 1);
        g_csrc[pos] = src[e];
    }
}

// ---------------- aggregation: z[v] = (1+eps)*h[v] + sum_{u in N(v)} h[u] ----------------
__global__ void agg_kernel(const float* __restrict__ h, float* __restrict__ z,
                           const float* __restrict__ eps, int layer) {
    int gw = (blockIdx.x * blockDim.x + threadIdx.x) >> 5;
    if (gw >= N_NODES) return;
    int lane = threadIdx.x & 31;
    float e1 = 1.0f + __ldg(&eps[layer]);
    const float4* h4 = (const float4*)h;

    float4 a0 = h4[(size_t)gw * 64 + lane];
    float4 a1 = h4[(size_t)gw * 64 + lane + 32];
    a0.x *= e1; a0.y *= e1; a0.z *= e1; a0.w *= e1;
    a1.x *= e1; a1.y *= e1; a1.z *= e1; a1.w *= e1;

    int beg = g_offs[gw], end = g_offs[gw + 1];
    int j = beg;
    for (; j + 1 < end; j += 2) {
        int u0 = g_csrc[j], u1 = g_csrc[j + 1];
        float4 b0 = h4[(size_t)u0 * 64 + lane];
        float4 b1 = h4[(size_t)u0 * 64 + lane + 32];
        float4 c0 = h4[(size_t)u1 * 64 + lane];
        float4 c1 = h4[(size_t)u1 * 64 + lane + 32];
        a0.x += b0.x + c0.x; a0.y += b0.y + c0.y; a0.z += b0.z + c0.z; a0.w += b0.w + c0.w;
        a1.x += b1.x + c1.x; a1.y += b1.y + c1.y; a1.z += b1.z + c1.z; a1.w += b1.w + c1.w;
    }
    if (j < end) {
        int u0 = g_csrc[j];
        float4 b0 = h4[(size_t)u0 * 64 + lane];
        float4 b1 = h4[(size_t)u0 * 64 + lane + 32];
        a0.x += b0.x; a0.y += b0.y; a0.z += b0.z; a0.w += b0.w;
        a1.x += b1.x; a1.y += b1.y; a1.z += b1.z; a1.w += b1.w;
    }
    float4* z4 = (float4*)z;
    z4[(size_t)gw * 64 + lane]      = a0;
    z4[(size_t)gw * 64 + lane + 32] = a1;
}

// ---------------- packed-f32x2 GEMM ----------------
__device__ __forceinline__ unsigned long long ffma2(unsigned long long a,
                                                    unsigned long long b,
                                                    unsigned long long c) {
    unsigned long long d;
    asm("fma.rn.f32x2 %0, %1, %2, %3;" : "=l"(d) : "l"(a), "l"(b), "l"(c));
    return d;
}
__device__ __forceinline__ unsigned long long pack2(float x) {
    unsigned long long d;
    asm("mov.b64 %0, {%1, %1};" : "=l"(d) : "f"(x));
    return d;
}

// EPI: 0 = relu(C + bias), 1 = relu(BN(C + bias)), 2 = C + bias
template <int EPI>
__global__ __launch_bounds__(256, 4)
void gemm_kernel(const float* __restrict__ A, const float* __restrict__ B,
                 float* __restrict__ C, int M, int N,
                 const float* __restrict__ bias,
                 const float* __restrict__ bn_g, const float* __restrict__ bn_b,
                 const float* __restrict__ bn_m, const float* __restrict__ bn_v) {
    __shared__ float As[16][128];
    __shared__ float Bs[16][64];
    const int tid = threadIdx.x;
    const int bm = blockIdx.y * 128, bn = blockIdx.x * 64;
    const int arow = tid >> 2, acol = (tid & 3) * 4;
    const int brow = tid >> 4, bcol = (tid & 15) * 4;
    const int tx = tid & 15, ty = tid >> 4;

    unsigned long long acc[4][4];
    #pragma unroll
    for (int p = 0; p < 4; p++)
        #pragma unroll
        for (int q = 0; q < 4; q++) acc[p][q] = 0ull;

    for (int k0 = 0; k0 < DK; k0 += 16) {
        #pragma unroll
        for (int r = 0; r < 2; r++) {
            int m = arow + r * 64;
            float4 v = *(const float4*)(A + (size_t)(bm + m) * DK + k0 + acol);
            As[acol + 0][m] = v.x; As[acol + 1][m] = v.y;
            As[acol + 2][m] = v.z; As[acol + 3][m] = v.w;
        }
        *(float4*)&Bs[brow][bcol] = *(const float4*)(B + (size_t)(k0 + brow) * N + bn + bcol);
        __syncthreads();
        #pragma unroll
        for (int k = 0; k < 16; k++) {
            ulonglong2 a01 = *(const ulonglong2*)&As[k][ty * 8];
            ulonglong2 a23 = *(const ulonglong2*)&As[k][ty * 8 + 4];
            float4 bv = *(const float4*)&Bs[k][tx * 4];
            unsigned long long bb0 = pack2(bv.x), bb1 = pack2(bv.y);
            unsigned long long bb2 = pack2(bv.z), bb3 = pack2(bv.w);
            acc[0][0] = ffma2(a01.x, bb0, acc[0][0]);
            acc[0][1] = ffma2(a01.x, bb1, acc[0][1]);
            acc[0][2] = ffma2(a01.x, bb2, acc[0][2]);
            acc[0][3] = ffma2(a01.x, bb3, acc[0][3]);
            acc[1][0] = ffma2(a01.y, bb0, acc[1][0]);
            acc[1][1] = ffma2(a01.y, bb1, acc[1][1]);
            acc[1][2] = ffma2(a01.y, bb2, acc[1][2]);
            acc[1][3] = ffma2(a01.y, bb3, acc[1][3]);
            acc[2][0] = ffma2(a23.x, bb0, acc[2][0]);
            acc[2][1] = ffma2(a23.x, bb1, acc[2][1]);
            acc[2][2] = ffma2(a23.x, bb2, acc[2][2]);
            acc[2][3] = ffma2(a23.x, bb3, acc[2][3]);
            acc[3][0] = ffma2(a23.y, bb0, acc[3][0]);
            acc[3][1] = ffma2(a23.y, bb1, acc[3][1]);
            acc[3][2] = ffma2(a23.y, bb2, acc[3][2]);
            acc[3][3] = ffma2(a23.y, bb3, acc[3][3]);
        }
        __syncthreads();
    }

    // epilogue
    int ncol = bn + tx * 4;
    float sc[4], sh[4];
    #pragma unroll
    for (int q = 0; q < 4; q++) {
        int n = ncol + q;
        if (EPI == 1) {
            float s = bn_g[n] * rsqrtf(bn_v[n] + BN_EPS);
            sc[q] = s;
            sh[q] = (bias[n] - bn_m[n]) * s + bn_b[n];
        } else {
            sc[q] = 1.0f;
            sh[q] = bias[n];
        }
    }
    #pragma unroll
    for (int p = 0; p < 4; p++) {
        int m0 = bm + ty * 8 + 2 * p;
        int m1 = m0 + 1;
        float lo[4], hi[4];
        #pragma unroll
        for (int q = 0; q < 4; q++) {
            unsigned long long v = acc[p][q];
            lo[q] = __uint_as_float((unsigned)(v & 0xffffffffull));
            hi[q] = __uint_as_float((unsigned)(v >> 32));
            lo[q] = lo[q] * sc[q] + sh[q];
            hi[q] = hi[q] * sc[q] + sh[q];
            if (EPI != 2) {
                lo[q] = fmaxf(lo[q], 0.0f);
                hi[q] = fmaxf(hi[q], 0.0f);
            }
        }
        if (m0 < M) *(float4*)(C + (size_t)m0 * N + ncol) = make_float4(lo[0], lo[1], lo[2], lo[3]);
        if (m1 < M) *(float4*)(C + (size_t)m1 * N + ncol) = make_float4(hi[0], hi[1], hi[2], hi[3]);
    }
}

// ---------------- launch ----------------
extern "C" void kernel_launch(void* const* d_in, const int* in_sizes, int n_in,
                              void* d_out, int out_size) {
    const float* x    = (const float*)d_in[0];
    const int*   ei   = (const int*)d_in[1];
    const float* W1   = (const float*)d_in[2];
    const float* b1   = (const float*)d_in[3];
    const float* W2a  = (const float*)d_in[4];
    const float* b2a  = (const float*)d_in[5];
    const float* W2l  = (const float*)d_in[6];
    const float* b2l  = (const float*)d_in[7];
    const float* eps  = (const float*)d_in[8];
    const float* bng  = (const float*)d_in[9];
    const float* bnb  = (const float*)d_in[10];
    const float* bnm  = (const float*)d_in[11];
    const float* bnv  = (const float*)d_in[12];
    float* out = (float*)d_out;

    void* p;
    cudaGetSymbolAddress(&p, g_h);      float* h  = (float*)p;
    cudaGetSymbolAddress(&p, g_z);      float* z  = (float*)p;
    cudaGetSymbolAddress(&p, g_t);      float* t  = (float*)p;
    cudaGetSymbolAddress(&p, g_deg);    int* deg  = (int*)p;
    cudaGetSymbolAddress(&p, g_offs);   int* offs = (int*)p;
    cudaGetSymbolAddress(&p, g_cursor); int* cur  = (int*)p;

    const int* srcp = ei;
    const int* dstp = ei + N_EDGES;

    // CSR build
    cudaMemsetAsync(deg, 0, N_NODES * sizeof(int));
    count_kernel<<<(N_EDGES + 255) / 256, 256>>>(dstp);
    scan_kernel<<<1, 1024>>>();
    cudaMemcpyAsync(cur, offs, N_NODES * sizeof(int), cudaMemcpyDeviceToDevice);
    fill_kernel<<<(N_EDGES + 255) / 256, 256>>>(srcp, dstp);

    dim3 g256(4, 157);   // N=256, M=20000
    dim3 g128(2, 157);   // N=128

    const float* hin = x;
    for (int i = 0; i < 4; i++) {
        agg_kernel<<<2500, 256>>>(hin, z, eps, i);
        gemm_kernel<0><<<g256, 256>>>(z, W1 + (size_t)i * DK * DK, t, N_NODES, 256,
                                      b1 + i * 256, nullptr, nullptr, nullptr, nullptr);
        gemm_kernel<1><<<g256, 256>>>(t, W2a + (size_t)i * DK * DK, h, N_NODES, 256,
                                      b2a + i * 256, bng + i * 256, bnb + i * 256,
                                      bnm + i * 256, bnv + i * 256);
        hin = h;
    }
    agg_kernel<<<2500, 256>>>(hin, z, eps, 4);
    gemm_kernel<0><<<g256, 256>>>(z, W1 + (size_t)4 * DK * DK, t, N_NODES, 256,
                                  b1 + 4 * 256, nullptr, nullptr, nullptr, nullptr);
    gemm_kernel<2><<<g128, 256>>>(t, W2l, out, N_NODES, 128,
                                  b2l, nullptr, nullptr, nullptr, nullptr);
}

// round 3
// speedup vs baseline: 1.5862x; 1.5862x over previous
#include <cuda_runtime.h>
#include <cuda_bf16.h>
#include <cstdint>

#define N_NODES 20000
#define N_EDGES 320000
#define DK      256
#define M_PAD   20096   // 157 * 128
#define BN_EPS  1e-5f

// ---------------- static scratch ----------------
__device__ float g_h[M_PAD * DK];
__device__ float g_z[M_PAD * DK];
__device__ float g_t[M_PAD * DK];
__device__ int   g_deg[N_NODES];
__device__ int   g_offs[N_NODES + 1];
__device__ int   g_cursor[N_NODES];
__device__ int   g_csrc[N_EDGES];
// pre-split transposed weights: layout [n][k], K-major (K=256 always)
// mats 0-4: W1[i] @ i*65536 ; 5-8: W2a[i] @ (5+i)*65536 ; 9: W2_last (128x256)
__device__ __nv_bfloat16 g_bhi[622592];
__device__ __nv_bfloat16 g_blo[622592];

// ---------------- helpers ----------------
__device__ __forceinline__ uint32_t smem_u32(const void* p) {
    uint32_t a;
    asm("{ .reg .u64 t; cvta.to.shared.u64 t, %1; cvt.u32.u64 %0, t; }" : "=r"(a) : "l"(p));
    return a;
}
__device__ __forceinline__ uint32_t sw128(uint32_t off) { return off ^ ((off >> 3) & 0x70); }

__device__ __forceinline__ void ldm_x4(uint32_t& r0, uint32_t& r1, uint32_t& r2, uint32_t& r3,
                                       uint32_t addr) {
    asm volatile("ldmatrix.sync.aligned.m8n8.x4.shared.b16 {%0,%1,%2,%3}, [%4];"
                 : "=r"(r0), "=r"(r1), "=r"(r2), "=r"(r3) : "r"(addr));
}
__device__ __forceinline__ void mma_bf16(float* d, const uint32_t* a, const uint32_t* b) {
    asm volatile(
        "mma.sync.aligned.m16n8k16.row.col.f32.bf16.bf16.f32 "
        "{%0,%1,%2,%3}, {%4,%5,%6,%7}, {%8,%9}, {%0,%1,%2,%3};"
        : "+f"(d[0]), "+f"(d[1]), "+f"(d[2]), "+f"(d[3])
        : "r"(a[0]), "r"(a[1]), "r"(a[2]), "r"(a[3]), "r"(b[0]), "r"(b[1]));
}

// ---------------- CSR build ----------------
__global__ void count_kernel(const int* __restrict__ dst) {
    int e = blockIdx.x * blockDim.x + threadIdx.x;
    if (e < N_EDGES) atomicAdd(&g_deg[dst[e]], 1);
}

__global__ void scan_kernel() {
    __shared__ int carry;
    __shared__ int wsum[32];
    int tid = threadIdx.x, lane = tid & 31, wid = tid >> 5;
    if (tid == 0) carry = 0;
    __syncthreads();
    for (int base = 0; base < N_NODES; base += 1024) {
        int i = base + tid;
        int v = (i < N_NODES) ? g_deg[i] : 0;
        int s = v;
        #pragma unroll
        for (int d = 1; d < 32; d <<= 1) {
            int t = __shfl_up_sync(0xffffffffu, s, d);
            if (lane >= d) s += t;
        }
        if (lane == 31) wsum[wid] = s;
        __syncthreads();
        if (wid == 0) {
            int ws = wsum[lane];
            #pragma unroll
            for (int d = 1; d < 32; d <<= 1) {
                int t = __shfl_up_sync(0xffffffffu, ws, d);
                if (lane >= d) ws += t;
            }
            wsum[lane] = ws;
        }
        __syncthreads();
        int excl = s - v + (wid > 0 ? wsum[wid - 1] : 0) + carry;
        if (i < N_NODES) g_offs[i] = excl;
        int total = wsum[31];
        __syncthreads();
        if (tid == 0) carry += total;
        __syncthreads();
    }
    if (tid == 0) g_offs[N_NODES] = carry;
}

__global__ void fill_kernel(const int* __restrict__ src, const int* __restrict__ dst) {
    int e = blockIdx.x * blockDim.x + threadIdx.x;
    if (e < N_EDGES) {
        int d = dst[e];
        int pos = atomicAdd(&g_cursor[d], 1);
        g_csrc[pos] = src[e];
    }
}

// ---------------- weight transpose + hi/lo split ----------------
__global__ void split_w(const float* __restrict__ src, int N, int dstOff, int total) {
    int i = blockIdx.x * blockDim.x + threadIdx.x;
    if (i >= total) return;
    int n = i >> 8, k = i & 255;
    float v = src[k * N + n];
    __nv_bfloat16 h = __float2bfloat16(v);
    float hf = __bfloat162float(h);
    g_bhi[dstOff + i] = h;
    g_blo[dstOff + i] = __float2bfloat16(v - hf);
}

// ---------------- aggregation ----------------
__global__ void agg_kernel(const float* __restrict__ h, float* __restrict__ z,
                           const float* __restrict__ eps, int layer) {
    int gw = (blockIdx.x * blockDim.x + threadIdx.x) >> 5;
    if (gw >= N_NODES) return;
    int lane = threadIdx.x & 31;
    float e1 = 1.0f + __ldg(&eps[layer]);
    const float4* h4 = (const float4*)h;

    float4 a0 = h4[(size_t)gw * 64 + lane];
    float4 a1 = h4[(size_t)gw * 64 + lane + 32];
    a0.x *= e1; a0.y *= e1; a0.z *= e1; a0.w *= e1;
    a1.x *= e1; a1.y *= e1; a1.z *= e1; a1.w *= e1;

    int beg = g_offs[gw], end = g_offs[gw + 1];
    int j = beg;
    for (; j + 1 < end; j += 2) {
        int u0 = g_csrc[j], u1 = g_csrc[j + 1];
        float4 b0 = h4[(size_t)u0 * 64 + lane];
        float4 b1 = h4[(size_t)u0 * 64 + lane + 32];
        float4 c0 = h4[(size_t)u1 * 64 + lane];
        float4 c1 = h4[(size_t)u1 * 64 + lane + 32];
        a0.x += b0.x + c0.x; a0.y += b0.y + c0.y; a0.z += b0.z + c0.z; a0.w += b0.w + c0.w;
        a1.x += b1.x + c1.x; a1.y += b1.y + c1.y; a1.z += b1.z + c1.z; a1.w += b1.w + c1.w;
    }
    if (j < end) {
        int u0 = g_csrc[j];
        float4 b0 = h4[(size_t)u0 * 64 + lane];
        float4 b1 = h4[(size_t)u0 * 64 + lane + 32];
        a0.x += b0.x; a0.y += b0.y; a0.z += b0.z; a0.w += b0.w;
        a1.x += b1.x; a1.y += b1.y; a1.z += b1.z; a1.w += b1.w;
    }
    float4* z4 = (float4*)z;
    z4[(size_t)gw * 64 + lane]      = a0;
    z4[(size_t)gw * 64 + lane + 32] = a1;
}

// ---------------- HMMA GEMM: C[M,NB] = A[M,256] @ B^T (3-term bf16 split) ----------------
// CTA: 256 thr, tile 128x128. Warp grid 4(M) x 2(N), warp tile 32x64.
// EPI: 0 = relu(C+bias), 1 = relu(BN(C+bias)), 2 = C+bias
template <int NB, int EPI>
__global__ __launch_bounds__(256, 2)
void gemm_hmma(const float* __restrict__ A,
               const __nv_bfloat16* __restrict__ Bhi, const __nv_bfloat16* __restrict__ Blo,
               float* __restrict__ C,
               const float* __restrict__ bias,
               const float* __restrict__ bn_g, const float* __restrict__ bn_b,
               const float* __restrict__ bn_m, const float* __restrict__ bn_v) {
    extern __shared__ __align__(1024) char smem[];
    constexpr int OFF_AHI = 0;
    constexpr int OFF_ALO = 16384;
    constexpr int OFF_BHI = 32768;
    constexpr int OFF_BLO = 49152;
    constexpr int OFF_SC  = 65536;
    constexpr int OFF_SH  = 65536 + 512;

    const int tid = threadIdx.x, wid = tid >> 5, lane = tid & 31;
    const int warpM = wid >> 1, warpN = wid & 1;
    const int bm = blockIdx.y * 128, bn = blockIdx.x * 128;
    const uint32_t sb = smem_u32(smem);

    float* SC = (float*)(smem + OFF_SC);
    float* SH = (float*)(smem + OFF_SH);
    if (tid < 128) {
        int n = bn + tid;
        if (EPI == 1) {
            float s = bn_g[n] * rsqrtf(bn_v[n] + BN_EPS);
            SC[tid] = s;
            SH[tid] = (bias[n] - bn_m[n]) * s + bn_b[n];
        } else {
            SC[tid] = 1.0f;
            SH[tid] = bias[n];
        }
    }

    float acc[2][8][4];
    #pragma unroll
    for (int f = 0; f < 2; f++)
        #pragma unroll
        for (int j = 0; j < 8; j++)
            #pragma unroll
            for (int q = 0; q < 4; q++) acc[f][j][q] = 0.0f;

    // fragment load addresses (relative offsets fixed per thread, swizzled per use)
    const int mbase = warpM * 32, nwbase = warpN * 64;

    for (int kc = 0; kc < 4; kc++) {
        __syncthreads();
        // stage A: fp32 -> bf16 hi/lo, 128 rows x 64 cols, SW128
        const float* Ab = A + (size_t)bm * DK + kc * 64;
        #pragma unroll
        for (int it = 0; it < 4; it++) {
            int item = tid + it * 256;
            int r = item >> 3, g = item & 7;
            const float4* p = (const float4*)(Ab + (size_t)r * DK + g * 8);
            float4 v0 = p[0], v1 = p[1];
            __nv_bfloat162 h0 = __floats2bfloat162_rn(v0.x, v0.y);
            __nv_bfloat162 h1 = __floats2bfloat162_rn(v0.z, v0.w);
            __nv_bfloat162 h2 = __floats2bfloat162_rn(v1.x, v1.y);
            __nv_bfloat162 h3 = __floats2bfloat162_rn(v1.z, v1.w);
            float2 f0 = __bfloat1622float2(h0), f1 = __bfloat1622float2(h1);
            float2 f2 = __bfloat1622float2(h2), f3 = __bfloat1622float2(h3);
            __nv_bfloat162 l0 = __floats2bfloat162_rn(v0.x - f0.x, v0.y - f0.y);
            __nv_bfloat162 l1 = __floats2bfloat162_rn(v0.z - f1.x, v0.w - f1.y);
            __nv_bfloat162 l2 = __floats2bfloat162_rn(v1.x - f2.x, v1.y - f2.y);
            __nv_bfloat162 l3 = __floats2bfloat162_rn(v1.z - f3.x, v1.w - f3.y);
            uint32_t off = sw128((uint32_t)(r * 128 + g * 16));
            *(uint4*)(smem + OFF_AHI + off) =
                make_uint4(*(uint32_t*)&h0, *(uint32_t*)&h1, *(uint32_t*)&h2, *(uint32_t*)&h3);
            *(uint4*)(smem + OFF_ALO + off) =
                make_uint4(*(uint32_t*)&l0, *(uint32_t*)&l1, *(uint32_t*)&l2, *(uint32_t*)&l3);
        }
        // stage B: pre-split bf16 [n][k] K-major, 128 rows x 64 cols
        #pragma unroll
        for (int it = 0; it < 4; it++) {
            int item = tid + it * 256;
            int n = item >> 3, g = item & 7;
            size_t si = (size_t)(bn + n) * DK + kc * 64 + g * 8;
            uint32_t off = sw128((uint32_t)(n * 128 + g * 16));
            *(uint4*)(smem + OFF_BHI + off) = *(const uint4*)(Bhi + si);
            *(uint4*)(smem + OFF_BLO + off) = *(const uint4*)(Blo + si);
        }
        __syncthreads();

        #pragma unroll
        for (int kk = 0; kk < 4; kk++) {
            // A fragments (hi + lo), one per 16-row block
            uint32_t ah[2][4], al[2][4];
            int arow = mbase + (lane & 15);
            uint32_t akb = kk * 32 + ((lane & 16) ? 16 : 0);
            #pragma unroll
            for (int f = 0; f < 2; f++) {
                uint32_t off = sw128((uint32_t)((arow + f * 16) * 128) + akb);
                ldm_x4(ah[f][0], ah[f][1], ah[f][2], ah[f][3], sb + OFF_AHI + off);
                ldm_x4(al[f][0], al[f][1], al[f][2], al[f][3], sb + OFF_ALO + off);
            }
            int brow = nwbase + (lane & 7) + ((lane & 16) ? 8 : 0);
            uint32_t bkb = kk * 32 + ((lane & 8) ? 16 : 0);
            #pragma unroll
            for (int jp = 0; jp < 4; jp++) {
                uint32_t off = sw128((uint32_t)((brow + jp * 16) * 128) + bkb);
                uint32_t bh[4], bl[4];
                ldm_x4(bh[0], bh[1], bh[2], bh[3], sb + OFF_BHI + off);
                ldm_x4(bl[0], bl[1], bl[2], bl[3], sb + OFF_BLO + off);
                #pragma unroll
                for (int f = 0; f < 2; f++) {
                    mma_bf16(acc[f][2 * jp],     ah[f], bh);
                    mma_bf16(acc[f][2 * jp + 1], ah[f], bh + 2);
                    mma_bf16(acc[f][2 * jp],     al[f], bh);
                    mma_bf16(acc[f][2 * jp + 1], al[f], bh + 2);
                    mma_bf16(acc[f][2 * jp],     ah[f], bl);
                    mma_bf16(acc[f][2 * jp + 1], ah[f], bl + 2);
                }
            }
        }
    }

    // epilogue
    #pragma unroll
    for (int f = 0; f < 2; f++) {
        int r0 = bm + mbase + f * 16 + (lane >> 2);
        #pragma unroll
        for (int j = 0; j < 8; j++) {
            int nloc = nwbase + j * 8 + (lane & 3) * 2;
            float s0 = SC[nloc], s1 = SC[nloc + 1];
            float t0 = SH[nloc], t1 = SH[nloc + 1];
            float v0 = acc[f][j][0] * s0 + t0;
            float v1 = acc[f][j][1] * s1 + t1;
            float v2 = acc[f][j][2] * s0 + t0;
            float v3 = acc[f][j][3] * s1 + t1;
            if (EPI != 2) {
                v0 = fmaxf(v0, 0.0f); v1 = fmaxf(v1, 0.0f);
                v2 = fmaxf(v2, 0.0f); v3 = fmaxf(v3, 0.0f);
            }
            int col = bn + nloc;
            if (r0 < N_NODES)
                *(float2*)(C + (size_t)r0 * NB + col) = make_float2(v0, v1);
            if (r0 + 8 < N_NODES)
                *(float2*)(C + (size_t)(r0 + 8) * NB + col) = make_float2(v2, v3);
        }
    }
}

// ---------------- launch ----------------
extern "C" void kernel_launch(void* const* d_in, const int* in_sizes, int n_in,
                              void* d_out, int out_size) {
    const float* x    = (const float*)d_in[0];
    const int*   ei   = (const int*)d_in[1];
    const float* W1   = (const float*)d_in[2];
    const float* b1   = (const float*)d_in[3];
    const float* W2a  = (const float*)d_in[4];
    const float* b2a  = (const float*)d_in[5];
    const float* W2l  = (const float*)d_in[6];
    const float* b2l  = (const float*)d_in[7];
    const float* eps  = (const float*)d_in[8];
    const float* bng  = (const float*)d_in[9];
    const float* bnb  = (const float*)d_in[10];
    const float* bnm  = (const float*)d_in[11];
    const float* bnv  = (const float*)d_in[12];
    float* out = (float*)d_out;

    void* p;
    cudaGetSymbolAddress(&p, g_h);      float* h  = (float*)p;
    cudaGetSymbolAddress(&p, g_z);      float* z  = (float*)p;
    cudaGetSymbolAddress(&p, g_t);      float* t  = (float*)p;
    cudaGetSymbolAddress(&p, g_deg);    int* deg  = (int*)p;
    cudaGetSymbolAddress(&p, g_offs);   int* offs = (int*)p;
    cudaGetSymbolAddress(&p, g_cursor); int* cur  = (int*)p;
    cudaGetSymbolAddress(&p, g_bhi);    const __nv_bfloat16* bhi = (const __nv_bfloat16*)p;
    cudaGetSymbolAddress(&p, g_blo);    const __nv_bfloat16* blo = (const __nv_bfloat16*)p;

    const int* srcp = ei;
    const int* dstp = ei + N_EDGES;

    const int SMEM = 65536 + 1024;
    cudaFuncSetAttribute(gemm_hmma<256, 0>, cudaFuncAttributeMaxDynamicSharedMemorySize, SMEM);
    cudaFuncSetAttribute(gemm_hmma<256, 1>, cudaFuncAttributeMaxDynamicSharedMemorySize, SMEM);
    cudaFuncSetAttribute(gemm_hmma<128, 2>, cudaFuncAttributeMaxDynamicSharedMemorySize, SMEM);

    // CSR build
    cudaMemsetAsync(deg, 0, N_NODES * sizeof(int));
    count_kernel<<<(N_EDGES + 255) / 256, 256>>>(dstp);
    scan_kernel<<<1, 1024>>>();
    cudaMemcpyAsync(cur, offs, N_NODES * sizeof(int), cudaMemcpyDeviceToDevice);
    fill_kernel<<<(N_EDGES + 255) / 256, 256>>>(srcp, dstp);

    // weight transpose + split
    for (int i = 0; i < 5; i++)
        split_w<<<256, 256>>>(W1 + (size_t)i * 65536, 256, i * 65536, 65536);
    for (int i = 0; i < 4; i++)
        split_w<<<256, 256>>>(W2a + (size_t)i * 65536, 256, (5 + i) * 65536, 65536);
    split_w<<<128, 256>>>(W2l, 128, 9 * 65536, 32768);

    dim3 g256(2, 157), g128(1, 157);

    const float* hin = x;
    for (int i = 0; i < 4; i++) {
        agg_kernel<<<2500, 256>>>(hin, z, eps, i);
        gemm_hmma<256, 0><<<g256, 256, SMEM>>>(z, bhi + (size_t)i * 65536, blo + (size_t)i * 65536,
                                               t, b1 + i * 256, nullptr, nullptr, nullptr, nullptr);
        gemm_hmma<256, 1><<<g256, 256, SMEM>>>(t, bhi + (size_t)(5 + i) * 65536, blo + (size_t)(5 + i) * 65536,
                                               h, b2a + i * 256, bng + i * 256, bnb + i * 256,
                                               bnm + i * 256, bnv + i * 256);
        hin = h;
    }
    agg_kernel<<<2500, 256>>>(hin, z, eps, 4);
    gemm_hmma<256, 0><<<g256, 256, SMEM>>>(z, bhi + (size_t)4 * 65536, blo + (size_t)4 * 65536,
                                           t, b1 + 4 * 256, nullptr, nullptr, nullptr, nullptr);
    gemm_hmma<128, 2><<<g128, 256, SMEM>>>(t, bhi + (size_t)9 * 65536, blo + (size_t)9 * 65536,
                                           out, b2l, nullptr, nullptr, nullptr, nullptr);
}

// round 5
// speedup vs baseline: 1.7373x; 1.0953x over previous
#include <cuda_runtime.h>
#include <cuda_bf16.h>
#include <cuda_fp16.h>
#include <cstdint>

#define N_NODES 20000
#define N_EDGES 320000
#define DK      256
#define M_PAD   20096   // 157 * 128
#define BN_EPS  1e-5f

// ---------------- static scratch ----------------
__device__ float  g_z[M_PAD * DK];
__device__ float  g_t[M_PAD * DK];
__device__ __half g_hf16[M_PAD * DK];   // fp16 mirror of current layer input (x or h)
__device__ int    g_deg[N_NODES];
__device__ int    g_offs[N_NODES + 1];
__device__ int    g_cursor[N_NODES];
__device__ int    g_csrc[N_EDGES];
// pre-split transposed weights, bf16 hi/lo: layout [n][k], K-major (K=256)
// mats 0-4: W1[i] @ i*65536 ; 5-8: W2a[i] @ (5+i)*65536 ; 9: W2_last (128x256) @ 9*65536
__device__ __nv_bfloat16 g_whi[622592];
__device__ __nv_bfloat16 g_wlo[622592];

// ---------------- helpers ----------------
__device__ __forceinline__ uint32_t smem_u32(const void* p) {
    uint32_t a;
    asm("{ .reg .u64 t; cvta.to.shared.u64 t, %1; cvt.u32.u64 %0, t; }" : "=r"(a) : "l"(p));
    return a;
}
__device__ __forceinline__ uint32_t sw128(uint32_t off) { return off ^ ((off >> 3) & 0x70); }

__device__ __forceinline__ void ldm_x4(uint32_t& r0, uint32_t& r1, uint32_t& r2, uint32_t& r3,
                                       uint32_t addr) {
    asm volatile("ldmatrix.sync.aligned.m8n8.x4.shared.b16 {%0,%1,%2,%3}, [%4];"
                 : "=r"(r0), "=r"(r1), "=r"(r2), "=r"(r3) : "r"(addr));
}
__device__ __forceinline__ void mma_bf16(float* d, const uint32_t* a, const uint32_t* b) {
    asm volatile(
        "mma.sync.aligned.m16n8k16.row.col.f32.bf16.bf16.f32 "
        "{%0,%1,%2,%3}, {%4,%5,%6,%7}, {%8,%9}, {%0,%1,%2,%3};"
        : "+f"(d[0]), "+f"(d[1]), "+f"(d[2]), "+f"(d[3])
        : "r"(a[0]), "r"(a[1]), "r"(a[2]), "r"(a[3]), "r"(b[0]), "r"(b[1]));
}

// ---------------- CSR build ----------------
__global__ void count_kernel(const int* __restrict__ dst) {
    int e = blockIdx.x * blockDim.x + threadIdx.x;
    if (e < N_EDGES) atomicAdd(&g_deg[dst[e]], 1);
}

__global__ void scan_kernel() {
    __shared__ int carry;
    __shared__ int wsum[32];
    int tid = threadIdx.x, lane = tid & 31, wid = tid >> 5;
    if (tid == 0) carry = 0;
    __syncthreads();
    for (int base = 0; base < N_NODES; base += 1024) {
        int i = base + tid;
        int v = (i < N_NODES) ? g_deg[i] : 0;
        int s = v;
        #pragma unroll
        for (int d = 1; d < 32; d <<= 1) {
            int t = __shfl_up_sync(0xffffffffu, s, d);
            if (lane >= d) s += t;
        }
        if (lane == 31) wsum[wid] = s;
        __syncthreads();
        if (wid == 0) {
            int ws = wsum[lane];
            #pragma unroll
            for (int d = 1; d < 32; d <<= 1) {
                int t = __shfl_up_sync(0xffffffffu, ws, d);
                if (lane >= d) ws += t;
            }
            wsum[lane] = ws;
        }
        __syncthreads();
        int excl = s - v + (wid > 0 ? wsum[wid - 1] : 0) + carry;
        if (i < N_NODES) { g_offs[i] = excl; g_cursor[i] = excl; }
        int total = wsum[31];
        __syncthreads();
        if (tid == 0) carry += total;
        __syncthreads();
    }
    if (tid == 0) g_offs[N_NODES] = carry;
}

__global__ void fill_kernel(const int* __restrict__ src, const int* __restrict__ dst) {
    int e = blockIdx.x * blockDim.x + threadIdx.x;
    if (e < N_NODES) g_deg[e] = 0;   // re-zero for next kernel_launch call
    if (e < N_EDGES) {
        int d = dst[e];
        int pos = atomicAdd(&g_cursor[d], 1);
        g_csrc[pos] = src[e];
    }
}

// ---------------- combined weight transpose + bf16 hi/lo split ----------------
__global__ void split_w_all(const float* __restrict__ W1, const float* __restrict__ W2a,
                            const float* __restrict__ W2l) {
    int i = blockIdx.x * blockDim.x + threadIdx.x;
    if (i >= 622592) return;
    const float* src;
    int local, N;
    if (i < 327680)      { src = W1  + (size_t)(i >> 16) * 65536;            local = i & 65535;  N = 256; }
    else if (i < 589824) { src = W2a + (size_t)((i - 327680) >> 16) * 65536; local = (i - 327680) & 65535; N = 256; }
    else                 { src = W2l;                                        local = i - 589824; N = 128; }
    int n = local >> 8, k = local & 255;
    float v = src[k * N + n];
    __nv_bfloat16 h = __float2bfloat16(v);
    g_whi[i] = h;
    g_wlo[i] = __float2bfloat16(v - __bfloat162float(h));
}

// ---------------- pack input x into f16 mirror ----------------
__global__ void pack_x(const float* __restrict__ x) {
    int i = blockIdx.x * blockDim.x + threadIdx.x;   // one per 4 floats
    if (i >= N_NODES * DK / 4) return;
    float4 v = ((const float4*)x)[i];
    __half2 p0 = __float22half2_rn(make_float2(v.x, v.y));
    __half2 p1 = __float22half2_rn(make_float2(v.z, v.w));
    ((uint2*)g_hf16)[i] = make_uint2(*(uint32_t*)&p0, *(uint32_t*)&p1);
}

// ---------------- aggregation (reads f16 mirror, fp32 accumulate) ----------------
__global__ void agg_kernel(const __half* __restrict__ h, float* __restrict__ z,
                           const float* __restrict__ eps, int layer) {
    int gw = (blockIdx.x * blockDim.x + threadIdx.x) >> 5;
    if (gw >= N_NODES) return;
    int lane = threadIdx.x & 31;
    float e1 = 1.0f + __ldg(&eps[layer]);
    const uint4* h4 = (const uint4*)h;   // row = 32 uint4 (256 halves)

    uint4 sv = h4[(size_t)gw * 32 + lane];
    float2 a0 = __half22float2(*(__half2*)&sv.x);
    float2 a1 = __half22float2(*(__half2*)&sv.y);
    float2 a2 = __half22float2(*(__half2*)&sv.z);
    float2 a3 = __half22float2(*(__half2*)&sv.w);
    a0.x *= e1; a0.y *= e1; a1.x *= e1; a1.y *= e1;
    a2.x *= e1; a2.y *= e1; a3.x *= e1; a3.y *= e1;

    int beg = g_offs[gw], end = g_offs[gw + 1];
    int j = beg;
    for (; j + 1 < end; j += 2) {
        int u0 = g_csrc[j], u1 = g_csrc[j + 1];
        uint4 b = h4[(size_t)u0 * 32 + lane];
        uint4 c = h4[(size_t)u1 * 32 + lane];
        float2 t;
        t = __half22float2(*(__half2*)&b.x); a0.x += t.x; a0.y += t.y;
        t = __half22float2(*(__half2*)&b.y); a1.x += t.x; a1.y += t.y;
        t = __half22float2(*(__half2*)&b.z); a2.x += t.x; a2.y += t.y;
        t = __half22float2(*(__half2*)&b.w); a3.x += t.x; a3.y += t.y;
        t = __half22float2(*(__half2*)&c.x); a0.x += t.x; a0.y += t.y;
        t = __half22float2(*(__half2*)&c.y); a1.x += t.x; a1.y += t.y;
        t = __half22float2(*(__half2*)&c.z); a2.x += t.x; a2.y += t.y;
        t = __half22float2(*(__half2*)&c.w); a3.x += t.x; a3.y += t.y;
    }
    if (j < end) {
        int u0 = g_csrc[j];
        uint4 b = h4[(size_t)u0 * 32 + lane];
        float2 t;
        t = __half22float2(*(__half2*)&b.x); a0.x += t.x; a0.y += t.y;
        t = __half22float2(*(__half2*)&b.y); a1.x += t.x; a1.y += t.y;
        t = __half22float2(*(__half2*)&b.z); a2.x += t.x; a2.y += t.y;
        t = __half22float2(*(__half2*)&b.w); a3.x += t.x; a3.y += t.y;
    }
    float4* z4 = (float4*)z;
    z4[(size_t)gw * 64 + lane * 2]     = make_float4(a0.x, a0.y, a1.x, a1.y);
    z4[(size_t)gw * 64 + lane * 2 + 1] = make_float4(a2.x, a2.y, a3.x, a3.y);
}

// ---------------- HMMA GEMM: C[M,NB] = A[M,256] @ B^T (3-term bf16 split) ----------------
// EPI: 0 = relu(C+bias) -> f32 ; 1 = relu(BN(C+bias)) -> f16 mirror ; 2 = C+bias -> f32
template <int NB, int EPI>
__global__ __launch_bounds__(256, 2)
void gemm_hmma(const float* __restrict__ A,
               const __nv_bfloat16* __restrict__ Bhi, const __nv_bfloat16* __restrict__ Blo,
               float* __restrict__ C, __half* __restrict__ Ch,
               const float* __restrict__ bias,
               const float* __restrict__ bn_g, const float* __restrict__ bn_b,
               const float* __restrict__ bn_m, const float* __restrict__ bn_v) {
    extern __shared__ __align__(1024) char smem[];
    constexpr int OFF_AHI = 0;
    constexpr int OFF_ALO = 16384;
    constexpr int OFF_BHI = 32768;
    constexpr int OFF_BLO = 49152;
    constexpr int OFF_SC  = 65536;
    constexpr int OFF_SH  = 65536 + 512;

    const int tid = threadIdx.x, wid = tid >> 5, lane = tid & 31;
    const int warpM = wid >> 1, warpN = wid & 1;
    const int bm = blockIdx.y * 128, bn = blockIdx.x * 128;
    const uint32_t sb = smem_u32(smem);

    float* SC = (float*)(smem + OFF_SC);
    float* SH = (float*)(smem + OFF_SH);
    if (tid < 128) {
        int n = bn + tid;
        if (EPI == 1) {
            float s = bn_g[n] * rsqrtf(bn_v[n] + BN_EPS);
            SC[tid] = s;
            SH[tid] = (bias[n] - bn_m[n]) * s + bn_b[n];
        } else {
            SC[tid] = 1.0f;
            SH[tid] = bias[n];
        }
    }

    float acc[2][8][4];
    #pragma unroll
    for (int f = 0; f < 2; f++)
        #pragma unroll
        for (int j = 0; j < 8; j++)
            #pragma unroll
            for (int q = 0; q < 4; q++) acc[f][j][q] = 0.0f;

    const int mbase = warpM * 32, nwbase = warpN * 64;

    for (int kc = 0; kc < 4; kc++) {
        __syncthreads();
        // stage A: fp32 -> bf16 hi/lo, 128 rows x 64 cols, SW128
        const float* Ab = A + (size_t)bm * DK + kc * 64;
        #pragma unroll
        for (int it = 0; it < 4; it++) {
            int item = tid + it * 256;
            int r = item >> 3, g = item & 7;
            const float4* p = (const float4*)(Ab + (size_t)r * DK + g * 8);
            float4 v0 = p[0], v1 = p[1];
            __nv_bfloat162 h0 = __floats2bfloat162_rn(v0.x, v0.y);
            __nv_bfloat162 h1 = __floats2bfloat162_rn(v0.z, v0.w);
            __nv_bfloat162 h2 = __floats2bfloat162_rn(v1.x, v1.y);
            __nv_bfloat162 h3 = __floats2bfloat162_rn(v1.z, v1.w);
            float2 f0 = __bfloat1622float2(h0), f1 = __bfloat1622float2(h1);
            float2 f2 = __bfloat1622float2(h2), f3 = __bfloat1622float2(h3);
            __nv_bfloat162 l0 = __floats2bfloat162_rn(v0.x - f0.x, v0.y - f0.y);
            __nv_bfloat162 l1 = __floats2bfloat162_rn(v0.z - f1.x, v0.w - f1.y);
            __nv_bfloat162 l2 = __floats2bfloat162_rn(v1.x - f2.x, v1.y - f2.y);
            __nv_bfloat162 l3 = __floats2bfloat162_rn(v1.z - f3.x, v1.w - f3.y);
            uint32_t off = sw128((uint32_t)(r * 128 + g * 16));
            *(uint4*)(smem + OFF_AHI + off) =
                make_uint4(*(uint32_t*)&h0, *(uint32_t*)&h1, *(uint32_t*)&h2, *(uint32_t*)&h3);
            *(uint4*)(smem + OFF_ALO + off) =
                make_uint4(*(uint32_t*)&l0, *(uint32_t*)&l1, *(uint32_t*)&l2, *(uint32_t*)&l3);
        }
        // stage B: pre-split bf16 [n][k] K-major, 128 rows x 64 cols
        #pragma unroll
        for (int it = 0; it < 4; it++) {
            int item = tid + it * 256;
            int n = item >> 3, g = item & 7;
            size_t si = (size_t)(bn + n) * DK + kc * 64 + g * 8;
            uint32_t off = sw128((uint32_t)(n * 128 + g * 16));
            *(uint4*)(smem + OFF_BHI + off) = *(const uint4*)(Bhi + si);
            *(uint4*)(smem + OFF_BLO + off) = *(const uint4*)(Blo + si);
        }
        __syncthreads();

        #pragma unroll
        for (int kk = 0; kk < 4; kk++) {
            uint32_t ah[2][4], al[2][4];
            int arow = mbase + (lane & 15);
            uint32_t akb = kk * 32 + ((lane & 16) ? 16 : 0);
            #pragma unroll
            for (int f = 0; f < 2; f++) {
                uint32_t off = sw128((uint32_t)((arow + f * 16) * 128) + akb);
                ldm_x4(ah[f][0], ah[f][1], ah[f][2], ah[f][3], sb + OFF_AHI + off);
                ldm_x4(al[f][0], al[f][1], al[f][2], al[f][3], sb + OFF_ALO + off);
            }
            int brow = nwbase + (lane & 7) + ((lane & 16) ? 8 : 0);
            uint32_t bkb = kk * 32 + ((lane & 8) ? 16 : 0);
            #pragma unroll
            for (int jp = 0; jp < 4; jp++) {
                uint32_t off = sw128((uint32_t)((brow + jp * 16) * 128) + bkb);
                uint32_t bh[4], bl[4];
                ldm_x4(bh[0], bh[1], bh[2], bh[3], sb + OFF_BHI + off);
                ldm_x4(bl[0], bl[1], bl[2], bl[3], sb + OFF_BLO + off);
                #pragma unroll
                for (int f = 0; f < 2; f++) {
                    mma_bf16(acc[f][2 * jp],     ah[f], bh);
                    mma_bf16(acc[f][2 * jp + 1], ah[f], bh + 2);
                    mma_bf16(acc[f][2 * jp],     al[f], bh);
                    mma_bf16(acc[f][2 * jp + 1], al[f], bh + 2);
                    mma_bf16(acc[f][2 * jp],     ah[f], bl);
                    mma_bf16(acc[f][2 * jp + 1], ah[f], bl + 2);
                }
            }
        }
    }

    // epilogue
    #pragma unroll
    for (int f = 0; f < 2; f++) {
        int r0 = bm + mbase + f * 16 + (lane >> 2);
        #pragma unroll
        for (int j = 0; j < 8; j++) {
            int nloc = nwbase + j * 8 + (lane & 3) * 2;
            float s0 = SC[nloc], s1 = SC[nloc + 1];
            float t0 = SH[nloc], t1 = SH[nloc + 1];
            float v0 = acc[f][j][0] * s0 + t0;
            float v1 = acc[f][j][1] * s1 + t1;
            float v2 = acc[f][j][2] * s0 + t0;
            float v3 = acc[f][j][3] * s1 + t1;
            if (EPI != 2) {
                v0 = fmaxf(v0, 0.0f); v1 = fmaxf(v1, 0.0f);
                v2 = fmaxf(v2, 0.0f); v3 = fmaxf(v3, 0.0f);
            }
            int col = bn + nloc;
            if (EPI == 1) {
                __half2 p0 = __float22half2_rn(make_float2(v0, v1));
                __half2 p1 = __float22half2_rn(make_float2(v2, v3));
                if (r0 < N_NODES)
                    *(__half2*)(Ch + (size_t)r0 * NB + col) = p0;
                if (r0 + 8 < N_NODES)
                    *(__half2*)(Ch + (size_t)(r0 + 8) * NB + col) = p1;
            } else {
                if (r0 < N_NODES)
                    *(float2*)(C + (size_t)r0 * NB + col) = make_float2(v0, v1);
                if (r0 + 8 < N_NODES)
                    *(float2*)(C + (size_t)(r0 + 8) * NB + col) = make_float2(v2, v3);
            }
        }
    }
}

// ---------------- launch ----------------
extern "C" void kernel_launch(void* const* d_in, const int* in_sizes, int n_in,
                              void* d_out, int out_size) {
    const float* x    = (const float*)d_in[0];
    const int*   ei   = (const int*)d_in[1];
    const float* W1   = (const float*)d_in[2];
    const float* b1   = (const float*)d_in[3];
    const float* W2a  = (const float*)d_in[4];
    const float* b2a  = (const float*)d_in[5];
    const float* W2l  = (const float*)d_in[6];
    const float* b2l  = (const float*)d_in[7];
    const float* eps  = (const float*)d_in[8];
    const float* bng  = (const float*)d_in[9];
    const float* bnb  = (const float*)d_in[10];
    const float* bnm  = (const float*)d_in[11];
    const float* bnv  = (const float*)d_in[12];
    float* out = (float*)d_out;

    void* p;
    cudaGetSymbolAddress(&p, g_z);    float*  z  = (float*)p;
    cudaGetSymbolAddress(&p, g_t);    float*  t  = (float*)p;
    cudaGetSymbolAddress(&p, g_hf16); __half* hf = (__half*)p;
    cudaGetSymbolAddress(&p, g_whi);  const __nv_bfloat16* whi = (const __nv_bfloat16*)p;
    cudaGetSymbolAddress(&p, g_wlo);  const __nv_bfloat16* wlo = (const __nv_bfloat16*)p;

    const int* srcp = ei;
    const int* dstp = ei + N_EDGES;

    const int SMEM = 65536 + 1024;
    cudaFuncSetAttribute(gemm_hmma<256, 0>, cudaFuncAttributeMaxDynamicSharedMemorySize, SMEM);
    cudaFuncSetAttribute(gemm_hmma<256, 1>, cudaFuncAttributeMaxDynamicSharedMemorySize, SMEM);
    cudaFuncSetAttribute(gemm_hmma<128, 2>, cudaFuncAttributeMaxDynamicSharedMemorySize, SMEM);

    // CSR build (deg re-zeroed by fill; cursor init by scan)
    count_kernel<<<(N_EDGES + 255) / 256, 256>>>(dstp);
    scan_kernel<<<1, 1024>>>();
    fill_kernel<<<(N_EDGES + 255) / 256, 256>>>(srcp, dstp);

    // weight transpose + split (single launch) ; pack x into f16 mirror
    split_w_all<<<(622592 + 255) / 256, 256>>>(W1, W2a, W2l);
    pack_x<<<(N_NODES * DK / 4 + 255) / 256, 256>>>(x);

    dim3 g256(2, 157), g128(1, 157);

    for (int i = 0; i < 4; i++) {
        agg_kernel<<<2500, 256>>>(hf, z, eps, i);
        gemm_hmma<256, 0><<<g256, 256, SMEM>>>(z, whi + (size_t)i * 65536, wlo + (size_t)i * 65536,
                                               t, nullptr, b1 + i * 256,
                                               nullptr, nullptr, nullptr, nullptr);
        gemm_hmma<256, 1><<<g256, 256, SMEM>>>(t, whi + (size_t)(5 + i) * 65536, wlo + (size_t)(5 + i) * 65536,
                                               nullptr, hf, b2a + i * 256,
                                               bng + i * 256, bnb + i * 256, bnm + i * 256, bnv + i * 256);
    }
    agg_kernel<<<2500, 256>>>(hf, z, eps, 4);
    gemm_hmma<256, 0><<<g256, 256, SMEM>>>(z, whi + (size_t)4 * 65536, wlo + (size_t)4 * 65536,
                                           t, nullptr, b1 + 4 * 256,
                                           nullptr, nullptr, nullptr, nullptr);
    gemm_hmma<128, 2><<<g128, 256, SMEM>>>(t, whi + (size_t)9 * 65536, wlo + (size_t)9 * 65536,
                                           out, nullptr, b2l,
                                           nullptr, nullptr, nullptr, nullptr);
}

// round 8
// speedup vs baseline: 1.9897x; 1.1453x over previous
#include <cuda_runtime.h>
#include <cuda_fp16.h>
#include <cstdint>

#define N_NODES 20000
#define N_EDGES 320000
#define DK      256
#define M_PAD   20096   // 157 * 128
#define BN_EPS  1e-5f

// ---------------- static scratch ----------------
// All activations fp16, stored with per-layer static scale 16^-(i+1) folded into epilogues.
__device__ __half g_zh[M_PAD * DK];     // aggregated features (GEMM1 input)
__device__ __half g_th[M_PAD * DK];     // hidden after first MLP layer (GEMM2 input)
__device__ __half g_hf16[M_PAD * DK];   // layer input mirror (x or h)
__device__ int    g_deg[N_NODES];
__device__ int    g_offs[N_NODES + 1];
__device__ int    g_cursor[N_NODES];
__device__ int    g_csrc[N_EDGES];
// transposed fp16 hi/lo weights: layout [n][k], K-major (K=256)
// mats 0-4: W1[i] @ i*65536 ; 5-8: W2a[i] @ (5+i)*65536 ; 9: W2_last (128x256) @ 9*65536
__device__ __half g_whi[622592];
__device__ __half g_wlo[622592];

// ---------------- helpers ----------------
__device__ __forceinline__ uint32_t smem_u32(const void* p) {
    uint32_t a;
    asm("{ .reg .u64 t; cvta.to.shared.u64 t, %1; cvt.u32.u64 %0, t; }" : "=r"(a) : "l"(p));
    return a;
}
__device__ __forceinline__ uint32_t sw128(uint32_t off) { return off ^ ((off >> 3) & 0x70); }

__device__ __forceinline__ void ldm_x4(uint32_t& r0, uint32_t& r1, uint32_t& r2, uint32_t& r3,
                                       uint32_t addr) {
    asm volatile("ldmatrix.sync.aligned.m8n8.x4.shared.b16 {%0,%1,%2,%3}, [%4];"
                 : "=r"(r0), "=r"(r1), "=r"(r2), "=r"(r3) : "r"(addr));
}
__device__ __forceinline__ void mma_f16(float* d, const uint32_t* a, const uint32_t* b) {
    asm volatile(
        "mma.sync.aligned.m16n8k16.row.col.f32.f16.f16.f32 "
        "{%0,%1,%2,%3}, {%4,%5,%6,%7}, {%8,%9}, {%0,%1,%2,%3};"
        : "+f"(d[0]), "+f"(d[1]), "+f"(d[2]), "+f"(d[3])
        : "r"(a[0]), "r"(a[1]), "r"(a[2]), "r"(a[3]), "r"(b[0]), "r"(b[1]));
}

// ---------------- CSR build ----------------
__global__ void count_kernel(const int* __restrict__ dst) {
    int e = blockIdx.x * blockDim.x + threadIdx.x;
    if (e < N_EDGES) atomicAdd(&g_deg[dst[e]], 1);
}

__global__ void scan_kernel() {
    __shared__ int carry;
    __shared__ int wsum[32];
    int tid = threadIdx.x, lane = tid & 31, wid = tid >> 5;
    if (tid == 0) carry = 0;
    __syncthreads();
    for (int base = 0; base < N_NODES; base += 1024) {
        int i = base + tid;
        int v = (i < N_NODES) ? g_deg[i] : 0;
        int s = v;
        #pragma unroll
        for (int d = 1; d < 32; d <<= 1) {
            int t = __shfl_up_sync(0xffffffffu, s, d);
            if (lane >= d) s += t;
        }
        if (lane == 31) wsum[wid] = s;
        __syncthreads();
        if (wid == 0) {
            int ws = wsum[lane];
            #pragma unroll
            for (int d = 1; d < 32; d <<= 1) {
                int t = __shfl_up_sync(0xffffffffu, ws, d);
                if (lane >= d) ws += t;
            }
            wsum[lane] = ws;
        }
        __syncthreads();
        int excl = s - v + (wid > 0 ? wsum[wid - 1] : 0) + carry;
        if (i < N_NODES) { g_offs[i] = excl; g_cursor[i] = excl; }
        int total = wsum[31];
        __syncthreads();
        if (tid == 0) carry += total;
        __syncthreads();
    }
    if (tid == 0) g_offs[N_NODES] = carry;
}

__global__ void fill_kernel(const int* __restrict__ src, const int* __restrict__ dst) {
    int e = blockIdx.x * blockDim.x + threadIdx.x;
    if (e < N_NODES) g_deg[e] = 0;   // re-zero for next kernel_launch call
    if (e < N_EDGES) {
        int d = dst[e];
        int pos = atomicAdd(&g_cursor[d], 1);
        g_csrc[pos] = src[e];
    }
}

// ---------------- weight transpose + fp16 hi/lo split ----------------
__global__ void split_w_all(const float* __restrict__ W1, const float* __restrict__ W2a,
                            const float* __restrict__ W2l) {
    int i = blockIdx.x * blockDim.x + threadIdx.x;
    if (i >= 622592) return;
    const float* src;
    int local, N;
    if (i < 327680)      { src = W1  + (size_t)(i >> 16) * 65536;            local = i & 65535;  N = 256; }
    else if (i < 589824) { src = W2a + (size_t)((i - 327680) >> 16) * 65536; local = (i - 327680) & 65535; N = 256; }
    else                 { src = W2l;                                        local = i - 589824; N = 128; }
    int n = local >> 8, k = local & 255;
    float v = src[k * N + n];
    __half h = __float2half_rn(v);
    g_whi[i] = h;
    g_wlo[i] = __float2half_rn(v - __half2float(h));
}

// ---------------- pack input x into f16 mirror (scale 1) ----------------
__global__ void pack_x(const float* __restrict__ x) {
    int i = blockIdx.x * blockDim.x + threadIdx.x;   // one per 4 floats
    if (i >= N_NODES * DK / 4) return;
    float4 v = ((const float4*)x)[i];
    __half2 p0 = __float22half2_rn(make_float2(v.x, v.y));
    __half2 p1 = __float22half2_rn(make_float2(v.z, v.w));
    ((uint2*)g_hf16)[i] = make_uint2(*(uint32_t*)&p0, *(uint32_t*)&p1);
}

// ---------------- aggregation: f16 in, fp32 accumulate, output scaled by 1/16 ----------------
__global__ void agg_kernel(const __half* __restrict__ h, __half* __restrict__ z,
                           const float* __restrict__ eps, int layer) {
    int gw = (blockIdx.x * blockDim.x + threadIdx.x) >> 5;
    if (gw >= N_NODES) return;
    int lane = threadIdx.x & 31;
    float e1 = 1.0f + __ldg(&eps[layer]);
    const uint4* h4 = (const uint4*)h;

    uint4 sv = h4[(size_t)gw * 32 + lane];
    float2 a0 = __half22float2(*(__half2*)&sv.x);
    float2 a1 = __half22float2(*(__half2*)&sv.y);
    float2 a2 = __half22float2(*(__half2*)&sv.z);
    float2 a3 = __half22float2(*(__half2*)&sv.w);
    a0.x *= e1; a0.y *= e1; a1.x *= e1; a1.y *= e1;
    a2.x *= e1; a2.y *= e1; a3.x *= e1; a3.y *= e1;

    int beg = g_offs[gw], end = g_offs[gw + 1];
    int j = beg;
    for (; j + 1 < end; j += 2) {
        int u0 = g_csrc[j], u1 = g_csrc[j + 1];
        uint4 b = h4[(size_t)u0 * 32 + lane];
        uint4 c = h4[(size_t)u1 * 32 + lane];
        float2 t;
        t = __half22float2(*(__half2*)&b.x); a0.x += t.x; a0.y += t.y;
        t = __half22float2(*(__half2*)&b.y); a1.x += t.x; a1.y += t.y;
        t = __half22float2(*(__half2*)&b.z); a2.x += t.x; a2.y += t.y;
        t = __half22float2(*(__half2*)&b.w); a3.x += t.x; a3.y += t.y;
        t = __half22float2(*(__half2*)&c.x); a0.x += t.x; a0.y += t.y;
        t = __half22float2(*(__half2*)&c.y); a1.x += t.x; a1.y += t.y;
        t = __half22float2(*(__half2*)&c.z); a2.x += t.x; a2.y += t.y;
        t = __half22float2(*(__half2*)&c.w); a3.x += t.x; a3.y += t.y;
    }
    if (j < end) {
        int u0 = g_csrc[j];
        uint4 b = h4[(size_t)u0 * 32 + lane];
        float2 t;
        t = __half22float2(*(__half2*)&b.x); a0.x += t.x; a0.y += t.y;
        t = __half22float2(*(__half2*)&b.y); a1.x += t.x; a1.y += t.y;
        t = __half22float2(*(__half2*)&b.z); a2.x += t.x; a2.y += t.y;
        t = __half22float2(*(__half2*)&b.w); a3.x += t.x; a3.y += t.y;
    }
    const float S = 0.0625f;   // 1/16 range compression per layer
    a0.x *= S; a0.y *= S; a1.x *= S; a1.y *= S;
    a2.x *= S; a2.y *= S; a3.x *= S; a3.y *= S;
    __half2 o0 = __float22half2_rn(a0), o1 = __float22half2_rn(a1);
    __half2 o2 = __float22half2_rn(a2), o3 = __float22half2_rn(a3);
    ((uint4*)z)[(size_t)gw * 32 + lane] =
        make_uint4(*(uint32_t*)&o0, *(uint32_t*)&o1, *(uint32_t*)&o2, *(uint32_t*)&o3);
}

// ---------------- fp16 HMMA GEMM: 2-term weight split, scaled activations ----------------
// EPI 0: stored = relu(acc + bias*rs)            -> f16   (t layer; SC=1, SH=bias*rs)
// EPI 1: stored = relu(acc*g' + ((bias-mean)g'+beta)*rs) -> f16 (h layer)
// EPI 2: out = acc*rs + bias                     -> f32   (final; rs = 16^5)
template <int NB, int EPI>
__global__ __launch_bounds__(256, 2)
void gemm_hmma(const __half* __restrict__ A,
               const __half* __restrict__ Bhi, const __half* __restrict__ Blo,
               float* __restrict__ C, __half* __restrict__ Ch,
               const float* __restrict__ bias,
               const float* __restrict__ bn_g, const float* __restrict__ bn_b,
               const float* __restrict__ bn_m, const float* __restrict__ bn_v,
               float rs) {
    extern __shared__ __align__(1024) char smem[];
    constexpr int OFF_A  = 0;
    constexpr int OFF_BH = 16384;
    constexpr int OFF_BL = 32768;
    constexpr int OFF_SC = 49152;
    constexpr int OFF_SH = 49152 + 512;

    const int tid = threadIdx.x, wid = tid >> 5, lane = tid & 31;
    const int warpM = wid >> 1, warpN = wid & 1;
    const int bm = blockIdx.y * 128, bn = blockIdx.x * 128;
    const uint32_t sb = smem_u32(smem);

    float* SC = (float*)(smem + OFF_SC);
    float* SH = (float*)(smem + OFF_SH);
    if (tid < 128) {
        int n = bn + tid;
        if (EPI == 1) {
            float s = bn_g[n] * rsqrtf(bn_v[n] + BN_EPS);
            SC[tid] = s;
            SH[tid] = ((bias[n] - bn_m[n]) * s + bn_b[n]) * rs;
        } else if (EPI == 0) {
            SC[tid] = 1.0f;
            SH[tid] = bias[n] * rs;
        } else {
            SC[tid] = rs;
            SH[tid] = bias[n];
        }
    }

    float acc[2][8][4];
    #pragma unroll
    for (int f = 0; f < 2; f++)
        #pragma unroll
        for (int j = 0; j < 8; j++)
            #pragma unroll
            for (int q = 0; q < 4; q++) acc[f][j][q] = 0.0f;

    const int mbase = warpM * 32, nwbase = warpN * 64;

    for (int kc = 0; kc < 4; kc++) {
        __syncthreads();
        // stage A chunk: fp16 direct copy, 128 rows x 64 cols, SW128
        #pragma unroll
        for (int it = 0; it < 4; it++) {
            int item = tid + it * 256;
            int r = item >> 3, g = item & 7;
            uint4 v = *(const uint4*)(A + (size_t)(bm + r) * DK + kc * 64 + g * 8);
            *(uint4*)(smem + OFF_A + sw128((uint32_t)(r * 128 + g * 16))) = v;
        }
        // stage B chunk: fp16 hi/lo [n][k] K-major, 128 rows x 64 cols
        #pragma unroll
        for (int it = 0; it < 4; it++) {
            int item = tid + it * 256;
            int n = item >> 3, g = item & 7;
            size_t si = (size_t)(bn + n) * DK + kc * 64 + g * 8;
            uint32_t off = sw128((uint32_t)(n * 128 + g * 16));
            *(uint4*)(smem + OFF_BH + off) = *(const uint4*)(Bhi + si);
            *(uint4*)(smem + OFF_BL + off) = *(const uint4*)(Blo + si);
        }
        __syncthreads();

        #pragma unroll
        for (int kk = 0; kk < 4; kk++) {
            uint32_t a[2][4];
            int arow = mbase + (lane & 15);
            uint32_t akb = kk * 32 + ((lane & 16) ? 16 : 0);
            #pragma unroll
            for (int f = 0; f < 2; f++) {
                uint32_t off = sw128((uint32_t)((arow + f * 16) * 128) + akb);
                ldm_x4(a[f][0], a[f][1], a[f][2], a[f][3], sb + OFF_A + off);
            }
            int brow = nwbase + (lane & 7) + ((lane & 16) ? 8 : 0);
            uint32_t bkb = kk * 32 + ((lane & 8) ? 16 : 0);
            #pragma unroll
            for (int jp = 0; jp < 4; jp++) {
                uint32_t off = sw128((uint32_t)((brow + jp * 16) * 128) + bkb);
                uint32_t bh[4], bl[4];
                ldm_x4(bh[0], bh[1], bh[2], bh[3], sb + OFF_BH + off);
                ldm_x4(bl[0], bl[1], bl[2], bl[3], sb + OFF_BL + off);
                #pragma unroll
                for (int f = 0; f < 2; f++) {
                    mma_f16(acc[f][2 * jp],     a[f], bh);
                    mma_f16(acc[f][2 * jp + 1], a[f], bh + 2);
                    mma_f16(acc[f][2 * jp],     a[f], bl);
                    mma_f16(acc[f][2 * jp + 1], a[f], bl + 2);
                }
            }
        }
    }

    // epilogue
    #pragma unroll
    for (int f = 0; f < 2; f++) {
        int r0 = bm + mbase + f * 16 + (lane >> 2);
        #pragma unroll
        for (int j = 0; j < 8; j++) {
            int nloc = nwbase + j * 8 + (lane & 3) * 2;
            float s0 = SC[nloc], s1 = SC[nloc + 1];
            float t0 = SH[nloc], t1 = SH[nloc + 1];
            float v0 = acc[f][j][0] * s0 + t0;
            float v1 = acc[f][j][1] * s1 + t1;
            float v2 = acc[f][j][2] * s0 + t0;
            float v3 = acc[f][j][3] * s1 + t1;
            if (EPI != 2) {
                v0 = fmaxf(v0, 0.0f); v1 = fmaxf(v1, 0.0f);
                v2 = fmaxf(v2, 0.0f); v3 = fmaxf(v3, 0.0f);
            }
            int col = bn + nloc;
            if (EPI == 2) {
                if (r0 < N_NODES)
                    *(float2*)(C + (size_t)r0 * NB + col) = make_float2(v0, v1);
                if (r0 + 8 < N_NODES)
                    *(float2*)(C + (size_t)(r0 + 8) * NB + col) = make_float2(v2, v3);
            } else {
                __half2 p0 = __float22half2_rn(make_float2(v0, v1));
                __half2 p1 = __float22half2_rn(make_float2(v2, v3));
                if (r0 < N_NODES)
                    *(__half2*)(Ch + (size_t)r0 * NB + col) = p0;
                if (r0 + 8 < N_NODES)
                    *(__half2*)(Ch + (size_t)(r0 + 8) * NB + col) = p1;
            }
        }
    }
}

// ---------------- launch ----------------
extern "C" void kernel_launch(void* const* d_in, const int* in_sizes, int n_in,
                              void* d_out, int out_size) {
    const float* x    = (const float*)d_in[0];
    const int*   ei   = (const int*)d_in[1];
    const float* W1   = (const float*)d_in[2];
    const float* b1   = (const float*)d_in[3];
    const float* W2a  = (const float*)d_in[4];
    const float* b2a  = (const float*)d_in[5];
    const float* W2l  = (const float*)d_in[6];
    const float* b2l  = (const float*)d_in[7];
    const float* eps  = (const float*)d_in[8];
    const float* bng  = (const float*)d_in[9];
    const float* bnb  = (const float*)d_in[10];
    const float* bnm  = (const float*)d_in[11];
    const float* bnv  = (const float*)d_in[12];
    float* out = (float*)d_out;

    void* p;
    cudaGetSymbolAddress(&p, g_zh);   __half* zh = (__half*)p;
    cudaGetSymbolAddress(&p, g_th);   __half* th = (__half*)p;
    cudaGetSymbolAddress(&p, g_hf16); __half* hf = (__half*)p;
    cudaGetSymbolAddress(&p, g_whi);  const __half* whi = (const __half*)p;
    cudaGetSymbolAddress(&p, g_wlo);  const __half* wlo = (const __half*)p;

    const int* srcp = ei;
    const int* dstp = ei + N_EDGES;

    const int SMEM = 49152 + 1024;
    cudaFuncSetAttribute(gemm_hmma<256, 0>, cudaFuncAttributeMaxDynamicSharedMemorySize, SMEM);
    cudaFuncSetAttribute(gemm_hmma<256, 1>, cudaFuncAttributeMaxDynamicSharedMemorySize, SMEM);
    cudaFuncSetAttribute(gemm_hmma<128, 2>, cudaFuncAttributeMaxDynamicSharedMemorySize, SMEM);

    // CSR build (deg re-zeroed by fill; cursor init by scan)
    count_kernel<<<(N_EDGES + 255) / 256, 256>>>(dstp);
    scan_kernel<<<1, 1024>>>();
    fill_kernel<<<(N_EDGES + 255) / 256, 256>>>(srcp, dstp);

    // weight transpose + split (single launch) ; pack x into f16 mirror
    split_w_all<<<(622592 + 255) / 256, 256>>>(W1, W2a, W2l);
    pack_x<<<(N_NODES * DK / 4 + 255) / 256, 256>>>(x);

    dim3 g256(2, 157), g128(1, 157);

    // rs for layer i = 16^-(i+1): undoes agg's 1/16 and tracks cumulative scale
    const float RS[5] = {1.0f / 16, 1.0f / 256, 1.0f / 4096, 1.0f / 65536, 1.0f / 1048576};

    for (int i = 0; i < 4; i++) {
        agg_kernel<<<2500, 256>>>(hf, zh, eps, i);
        gemm_hmma<256, 0><<<g256, 256, SMEM>>>(zh, whi + (size_t)i * 65536, wlo + (size_t)i * 65536,
                                               nullptr, th, b1 + i * 256,
                                               nullptr, nullptr, nullptr, nullptr, RS[i]);
        gemm_hmma<256, 1><<<g256, 256, SMEM>>>(th, whi + (size_t)(5 + i) * 65536, wlo + (size_t)(5 + i) * 65536,
                                               nullptr, hf, b2a + i * 256,
                                               bng + i * 256, bnb + i * 256, bnm + i * 256, bnv + i * 256,
                                               RS[i]);
    }
    agg_kernel<<<2500, 256>>>(hf, zh, eps, 4);
    gemm_hmma<256, 0><<<g256, 256, SMEM>>>(zh, whi + (size_t)4 * 65536, wlo + (size_t)4 * 65536,
                                           nullptr, th, b1 + 4 * 256,
                                           nullptr, nullptr, nullptr, nullptr, RS[4]);
    gemm_hmma<128, 2><<<g128, 256, SMEM>>>(th, whi + (size_t)9 * 65536, wlo + (size_t)9 * 65536,
                                           out, nullptr, b2l,
                                           nullptr, nullptr, nullptr, nullptr, 1048576.0f);
}

// round 10
// speedup vs baseline: 2.4699x; 1.2414x over previous
#include <cuda_runtime.h>
#include <cuda_fp16.h>
#include <cstdint>

#define N_NODES 20000
#define N_EDGES 320000
#define DK      256
#define M_PAD   20096   // 157 * 128
#define BN_EPS  1e-5f

// ---------------- static scratch ----------------
// All activations fp16, stored with per-layer static scale 16^-(i+1) folded into epilogues.
__device__ __half g_zh[M_PAD * DK];     // aggregated features (GEMM1 input)
__device__ __half g_th[M_PAD * DK];     // hidden after first MLP layer (GEMM2 input)
__device__ __half g_hf16[M_PAD * DK];   // layer input mirror (x or h)
__device__ int    g_deg[N_NODES];
__device__ int    g_offs[N_NODES + 1];
__device__ int    g_cursor[N_NODES];
__device__ int    g_csrc[N_EDGES];
// transposed fp16 hi/lo weights: layout [n][k], K-major (K=256)
// mats 0-4: W1[i] @ i*65536 ; 5-8: W2a[i] @ (5+i)*65536 ; 9: W2_last (128x256) @ 9*65536
__device__ __half g_whi[622592];
__device__ __half g_wlo[622592];

// ---------------- helpers ----------------
__device__ __forceinline__ uint32_t smem_u32(const void* p) {
    uint32_t a;
    asm("{ .reg .u64 t; cvta.to.shared.u64 t, %1; cvt.u32.u64 %0, t; }" : "=r"(a) : "l"(p));
    return a;
}
__device__ __forceinline__ uint32_t sw128(uint32_t off) { return off ^ ((off >> 3) & 0x70); }

__device__ __forceinline__ void ldm_x4(uint32_t& r0, uint32_t& r1, uint32_t& r2, uint32_t& r3,
                                       uint32_t addr) {
    asm volatile("ldmatrix.sync.aligned.m8n8.x4.shared.b16 {%0,%1,%2,%3}, [%4];"
                 : "=r"(r0), "=r"(r1), "=r"(r2), "=r"(r3) : "r"(addr));
}
__device__ __forceinline__ void mma_f16(float* d, const uint32_t* a, const uint32_t* b) {
    asm volatile(
        "mma.sync.aligned.m16n8k16.row.col.f32.f16.f16.f32 "
        "{%0,%1,%2,%3}, {%4,%5,%6,%7}, {%8,%9}, {%0,%1,%2,%3};"
        : "+f"(d[0]), "+f"(d[1]), "+f"(d[2]), "+f"(d[3])
        : "r"(a[0]), "r"(a[1]), "r"(a[2]), "r"(a[3]), "r"(b[0]), "r"(b[1]));
}

// ---------------- CSR build ----------------
__global__ void count_kernel(const int* __restrict__ dst) {
    int e = blockIdx.x * blockDim.x + threadIdx.x;
    if (e < N_EDGES) atomicAdd(&g_deg[dst[e]], 1);
}

__global__ void scan_kernel() {
    __shared__ int carry;
    __shared__ int wsum[32];
    int tid = threadIdx.x, lane = tid & 31, wid = tid >> 5;
    if (tid == 0) carry = 0;
    __syncthreads();
    for (int base = 0; base < N_NODES; base += 1024) {
        int i = base + tid;
        int v = (i < N_NODES) ? g_deg[i] : 0;
        int s = v;
        #pragma unroll
        for (int d = 1; d < 32; d <<= 1) {
            int t = __shfl_up_sync(0xffffffffu, s, d);
            if (lane >= d) s += t;
        }
        if (lane == 31) wsum[wid] = s;
        __syncthreads();
        if (wid == 0) {
            int ws = wsum[lane];
            #pragma unroll
            for (int d = 1; d < 32; d <<= 1) {
                int t = __shfl_up_sync(0xffffffffu, ws, d);
                if (lane >= d) ws += t;
            }
            wsum[lane] = ws;
        }
        __syncthreads();
        int excl = s - v + (wid > 0 ? wsum[wid - 1] : 0) + carry;
        if (i < N_NODES) { g_offs[i] = excl; g_cursor[i] = excl; }
        int total = wsum[31];
        __syncthreads();
        if (tid == 0) carry += total;
        __syncthreads();
    }
    if (tid == 0) g_offs[N_NODES] = carry;
}

__global__ void fill_kernel(const int* __restrict__ src, const int* __restrict__ dst) {
    int e = blockIdx.x * blockDim.x + threadIdx.x;
    if (e < N_NODES) g_deg[e] = 0;   // re-zero for next kernel_launch call
    if (e < N_EDGES) {
        int d = dst[e];
        int pos = atomicAdd(&g_cursor[d], 1);
        g_csrc[pos] = src[e];
    }
}

// ---------------- weight transpose/split + input pack, one launch ----------------
__global__ void prep_kernel(const float* __restrict__ W1, const float* __restrict__ W2a,
                            const float* __restrict__ W2l, const float* __restrict__ x) {
    int i = blockIdx.x * blockDim.x + threadIdx.x;
    if (i < 622592) {
        const float* src;
        int local, N;
        if (i < 327680)      { src = W1  + (size_t)(i >> 16) * 65536;            local = i & 65535;  N = 256; }
        else if (i < 589824) { src = W2a + (size_t)((i - 327680) >> 16) * 65536; local = (i - 327680) & 65535; N = 256; }
        else                 { src = W2l;                                        local = i - 589824; N = 128; }
        int n = local >> 8, k = local & 255;
        float v = src[k * N + n];
        __half h = __float2half_rn(v);
        g_whi[i] = h;
        g_wlo[i] = __float2half_rn(v - __half2float(h));
    } else {
        int j = i - 622592;                    // pack x: one per 4 floats
        if (j >= N_NODES * DK / 4) return;
        float4 v = ((const float4*)x)[j];
        __half2 p0 = __float22half2_rn(make_float2(v.x, v.y));
        __half2 p1 = __float22half2_rn(make_float2(v.z, v.w));
        ((uint2*)g_hf16)[j] = make_uint2(*(uint32_t*)&p0, *(uint32_t*)&p1);
    }
}

// ---------------- aggregation: f16 in, fp32 accumulate, output scaled by 1/16 ----------------
__global__ void agg_kernel(const __half* __restrict__ h, __half* __restrict__ z,
                           const float* __restrict__ eps, int layer) {
    int gw = (blockIdx.x * blockDim.x + threadIdx.x) >> 5;
    if (gw >= N_NODES) return;
    int lane = threadIdx.x & 31;
    float e1 = 1.0f + __ldg(&eps[layer]);
    const uint4* h4 = (const uint4*)h;

    uint4 sv = h4[(size_t)gw * 32 + lane];
    float2 a0 = __half22float2(*(__half2*)&sv.x);
    float2 a1 = __half22float2(*(__half2*)&sv.y);
    float2 a2 = __half22float2(*(__half2*)&sv.z);
    float2 a3 = __half22float2(*(__half2*)&sv.w);
    a0.x *= e1; a0.y *= e1; a1.x *= e1; a1.y *= e1;
    a2.x *= e1; a2.y *= e1; a3.x *= e1; a3.y *= e1;

    int beg = g_offs[gw], end = g_offs[gw + 1];
    int j = beg;
    for (; j + 1 < end; j += 2) {
        int u0 = g_csrc[j], u1 = g_csrc[j + 1];
        uint4 b = h4[(size_t)u0 * 32 + lane];
        uint4 c = h4[(size_t)u1 * 32 + lane];
        float2 t;
        t = __half22float2(*(__half2*)&b.x); a0.x += t.x; a0.y += t.y;
        t = __half22float2(*(__half2*)&b.y); a1.x += t.x; a1.y += t.y;
        t = __half22float2(*(__half2*)&b.z); a2.x += t.x; a2.y += t.y;
        t = __half22float2(*(__half2*)&b.w); a3.x += t.x; a3.y += t.y;
        t = __half22float2(*(__half2*)&c.x); a0.x += t.x; a0.y += t.y;
        t = __half22float2(*(__half2*)&c.y); a1.x += t.x; a1.y += t.y;
        t = __half22float2(*(__half2*)&c.z); a2.x += t.x; a2.y += t.y;
        t = __half22float2(*(__half2*)&c.w); a3.x += t.x; a3.y += t.y;
    }
    if (j < end) {
        int u0 = g_csrc[j];
        uint4 b = h4[(size_t)u0 * 32 + lane];
        float2 t;
        t = __half22float2(*(__half2*)&b.x); a0.x += t.x; a0.y += t.y;
        t = __half22float2(*(__half2*)&b.y); a1.x += t.x; a1.y += t.y;
        t = __half22float2(*(__half2*)&b.z); a2.x += t.x; a2.y += t.y;
        t = __half22float2(*(__half2*)&b.w); a3.x += t.x; a3.y += t.y;
    }
    const float S = 0.0625f;   // 1/16 range compression per layer
    a0.x *= S; a0.y *= S; a1.x *= S; a1.y *= S;
    a2.x *= S; a2.y *= S; a3.x *= S; a3.y *= S;
    __half2 o0 = __float22half2_rn(a0), o1 = __float22half2_rn(a1);
    __half2 o2 = __float22half2_rn(a2), o3 = __float22half2_rn(a3);
    ((uint4*)z)[(size_t)gw * 32 + lane] =
        make_uint4(*(uint32_t*)&o0, *(uint32_t*)&o1, *(uint32_t*)&o2, *(uint32_t*)&o3);
}

// ---------------- fp16 HMMA GEMM, tile 128(M)x64(N), 2-term weight split ----------------
// NB = row stride of output (256 or 128). Grid: (NB/64, 157).
// EPI 0: stored = relu(acc + bias*rs) -> f16
// EPI 1: stored = relu(acc*g' + ((bias-mean)g'+beta)*rs) -> f16
// EPI 2: out = acc*rs + bias -> f32
template <int NB, int EPI>
__global__ __launch_bounds__(256, 2)
void gemm_hmma(const __half* __restrict__ A,
               const __half* __restrict__ Bhi, const __half* __restrict__ Blo,
               float* __restrict__ C, __half* __restrict__ Ch,
               const float* __restrict__ bias,
               const float* __restrict__ bn_g, const float* __restrict__ bn_b,
               const float* __restrict__ bn_m, const float* __restrict__ bn_v,
               float rs) {
    extern __shared__ __align__(1024) char smem[];
    constexpr int OFF_A  = 0;        // 128 x 64 f16 = 16384
    constexpr int OFF_BH = 16384;    // 64 x 64 f16  = 8192
    constexpr int OFF_BL = 24576;    // 64 x 64 f16  = 8192
    constexpr int OFF_SC = 32768;    // 64 floats
    constexpr int OFF_SH = 33024;    // 64 floats

    const int tid = threadIdx.x, wid = tid >> 5, lane = tid & 31;
    const int warpM = wid >> 1, warpN = wid & 1;
    const int bm = blockIdx.y * 128, bn = blockIdx.x * 64;
    const uint32_t sb = smem_u32(smem);

    float* SC = (float*)(smem + OFF_SC);
    float* SH = (float*)(smem + OFF_SH);
    if (tid < 64) {
        int n = bn + tid;
        if (EPI == 1) {
            float s = bn_g[n] * rsqrtf(bn_v[n] + BN_EPS);
            SC[tid] = s;
            SH[tid] = ((bias[n] - bn_m[n]) * s + bn_b[n]) * rs;
        } else if (EPI == 0) {
            SC[tid] = 1.0f;
            SH[tid] = bias[n] * rs;
        } else {
            SC[tid] = rs;
            SH[tid] = bias[n];
        }
    }

    float acc[2][4][4];
    #pragma unroll
    for (int f = 0; f < 2; f++)
        #pragma unroll
        for (int j = 0; j < 4; j++)
            #pragma unroll
            for (int q = 0; q < 4; q++) acc[f][j][q] = 0.0f;

    const int mbase = warpM * 32, nwbase = warpN * 32;

    for (int kc = 0; kc < 4; kc++) {
        __syncthreads();
        // stage A chunk: fp16, 128 rows x 64 K-cols, SW128
        #pragma unroll
        for (int it = 0; it < 4; it++) {
            int item = tid + it * 256;
            int r = item >> 3, g = item & 7;
            uint4 v = *(const uint4*)(A + (size_t)(bm + r) * DK + kc * 64 + g * 8);
            *(uint4*)(smem + OFF_A + sw128((uint32_t)(r * 128 + g * 16))) = v;
        }
        // stage B chunk: fp16 hi/lo [n][k] K-major, 64 rows x 64 K-cols
        {
            int item = tid + 0;                // 256 threads x 2 iters = 512 items
            #pragma unroll
            for (int it = 0; it < 2; it++) {
                int n = item >> 3, g = item & 7;
                size_t si = (size_t)(bn + n) * DK + kc * 64 + g * 8;
                uint32_t off = sw128((uint32_t)(n * 128 + g * 16));
                *(uint4*)(smem + OFF_BH + off) = *(const uint4*)(Bhi + si);
                *(uint4*)(smem + OFF_BL + off) = *(const uint4*)(Blo + si);
                item += 256;
            }
        }
        __syncthreads();

        #pragma unroll
        for (int kk = 0; kk < 4; kk++) {
            uint32_t a[2][4];
            int arow = mbase + (lane & 15);
            uint32_t akb = kk * 32 + ((lane & 16) ? 16 : 0);
            #pragma unroll
            for (int f = 0; f < 2; f++) {
                uint32_t off = sw128((uint32_t)((arow + f * 16) * 128) + akb);
                ldm_x4(a[f][0], a[f][1], a[f][2], a[f][3], sb + OFF_A + off);
            }
            int brow = nwbase + (lane & 7) + ((lane & 16) ? 8 : 0);
            uint32_t bkb = kk * 32 + ((lane & 8) ? 16 : 0);
            #pragma unroll
            for (int jp = 0; jp < 2; jp++) {
                uint32_t off = sw128((uint32_t)((brow + jp * 16) * 128) + bkb);
                uint32_t bh[4], bl[4];
                ldm_x4(bh[0], bh[1], bh[2], bh[3], sb + OFF_BH + off);
                ldm_x4(bl[0], bl[1], bl[2], bl[3], sb + OFF_BL + off);
                #pragma unroll
                for (int f = 0; f < 2; f++) {
                    mma_f16(acc[f][2 * jp],     a[f], bh);
                    mma_f16(acc[f][2 * jp + 1], a[f], bh + 2);
                    mma_f16(acc[f][2 * jp],     a[f], bl);
                    mma_f16(acc[f][2 * jp + 1], a[f], bl + 2);
                }
            }
        }
    }

    // epilogue
    #pragma unroll
    for (int f = 0; f < 2; f++) {
        int r0 = bm + mbase + f * 16 + (lane >> 2);
        #pragma unroll
        for (int j = 0; j < 4; j++) {
            int nloc = nwbase + j * 8 + (lane & 3) * 2;
            float s0 = SC[nloc], s1 = SC[nloc + 1];
            float t0 = SH[nloc], t1 = SH[nloc + 1];
            float v0 = acc[f][j][0] * s0 + t0;
            float v1 = acc[f][j][1] * s1 + t1;
            float v2 = acc[f][j][2] * s0 + t0;
            float v3 = acc[f][j][3] * s1 + t1;
            if (EPI != 2) {
                v0 = fmaxf(v0, 0.0f); v1 = fmaxf(v1, 0.0f);
                v2 = fmaxf(v2, 0.0f); v3 = fmaxf(v3, 0.0f);
            }
            int col = bn + nloc;
            if (EPI == 2) {
                if (r0 < N_NODES)
                    *(float2*)(C + (size_t)r0 * NB + col) = make_float2(v0, v1);
                if (r0 + 8 < N_NODES)
                    *(float2*)(C + (size_t)(r0 + 8) * NB + col) = make_float2(v2, v3);
            } else {
                __half2 p0 = __float22half2_rn(make_float2(v0, v1));
                __half2 p1 = __float22half2_rn(make_float2(v2, v3));
                if (r0 < N_NODES)
                    *(__half2*)(Ch + (size_t)r0 * NB + col) = p0;
                if (r0 + 8 < N_NODES)
                    *(__half2*)(Ch + (size_t)(r0 + 8) * NB + col) = p1;
            }
        }
    }
}

// ---------------- launch ----------------
extern "C" void kernel_launch(void* const* d_in, const int* in_sizes, int n_in,
                              void* d_out, int out_size) {
    const float* x    = (const float*)d_in[0];
    const int*   ei   = (const int*)d_in[1];
    const float* W1   = (const float*)d_in[2];
    const float* b1   = (const float*)d_in[3];
    const float* W2a  = (const float*)d_in[4];
    const float* b2a  = (const float*)d_in[5];
    const float* W2l  = (const float*)d_in[6];
    const float* b2l  = (const float*)d_in[7];
    const float* eps  = (const float*)d_in[8];
    const float* bng  = (const float*)d_in[9];
    const float* bnb  = (const float*)d_in[10];
    const float* bnm  = (const float*)d_in[11];
    const float* bnv  = (const float*)d_in[12];
    float* out = (float*)d_out;

    void* p;
    cudaGetSymbolAddress(&p, g_zh);   __half* zh = (__half*)p;
    cudaGetSymbolAddress(&p, g_th);   __half* th = (__half*)p;
    cudaGetSymbolAddress(&p, g_hf16); __half* hf = (__half*)p;
    cudaGetSymbolAddress(&p, g_whi);  const __half* whi = (const __half*)p;
    cudaGetSymbolAddress(&p, g_wlo);  const __half* wlo = (const __half*)p;

    const int* srcp = ei;
    const int* dstp = ei + N_EDGES;

    const int SMEM = 33280 + 256;
    cudaFuncSetAttribute(gemm_hmma<256, 0>, cudaFuncAttributeMaxDynamicSharedMemorySize, SMEM);
    cudaFuncSetAttribute(gemm_hmma<256, 1>, cudaFuncAttributeMaxDynamicSharedMemorySize, SMEM);
    cudaFuncSetAttribute(gemm_hmma<128, 2>, cudaFuncAttributeMaxDynamicSharedMemorySize, SMEM);

    // CSR build (deg re-zeroed by fill; cursor init by scan)
    count_kernel<<<(N_EDGES + 255) / 256, 256>>>(dstp);
    scan_kernel<<<1, 1024>>>();
    fill_kernel<<<(N_EDGES + 255) / 256, 256>>>(srcp, dstp);

    // weight transpose/split + x pack, one launch
    prep_kernel<<<(622592 + 1280000 + 255) / 256, 256>>>(W1, W2a, W2l, x);

    dim3 g256(4, 157), g128(2, 157);

    // rs for layer i = 16^-(i+1): undoes agg's 1/16 and tracks cumulative scale
    const float RS[5] = {1.0f / 16, 1.0f / 256, 1.0f / 4096, 1.0f / 65536, 1.0f / 1048576};

    for (int i = 0; i < 4; i++) {
        agg_kernel<<<2500, 256>>>(hf, zh, eps, i);
        gemm_hmma<256, 0><<<g256, 256, SMEM>>>(zh, whi + (size_t)i * 65536, wlo + (size_t)i * 65536,
                                               nullptr, th, b1 + i * 256,
                                               nullptr, nullptr, nullptr, nullptr, RS[i]);
        gemm_hmma<256, 1><<<g256, 256, SMEM>>>(th, whi + (size_t)(5 + i) * 65536, wlo + (size_t)(5 + i) * 65536,
                                               nullptr, hf, b2a + i * 256,
                                               bng + i * 256, bnb + i * 256, bnm + i * 256, bnv + i * 256,
                                               RS[i]);
    }
    agg_kernel<<<2500, 256>>>(hf, zh, eps, 4);
    gemm_hmma<256, 0><<<g256, 256, SMEM>>>(zh, whi + (size_t)4 * 65536, wlo + (size_t)4 * 65536,
                                           nullptr, th, b1 + 4 * 256,
                                           nullptr, nullptr, nullptr, nullptr, RS[4]);
    gemm_hmma<128, 2><<<g128, 256, SMEM>>>(th, whi + (size_t)9 * 65536, wlo + (size_t)9 * 65536,
                                           out, nullptr, b2l,
                                           nullptr, nullptr, nullptr, nullptr, 1048576.0f);
}

// round 11
// speedup vs baseline: 3.1439x; 1.2729x over previous
#include <cuda_runtime.h>
#include <cuda_fp16.h>
#include <cstdint>

#define N_NODES 20000
#define N_EDGES 320000
#define DK      256
#define M_PAD   20096   // 157 * 128
#define BN_EPS  1e-5f

// ---------------- static scratch ----------------
// All activations fp16, stored with per-layer static scale 16^-(i+1) folded into epilogues.
__device__ __half g_zh[M_PAD * DK];     // aggregated features (GEMM1 input)
__device__ __half g_th[M_PAD * DK];     // hidden after first MLP layer (GEMM2 input)
__device__ __half g_hf16[M_PAD * DK];   // layer input mirror (x or h)
__device__ int    g_deg[N_NODES];
__device__ int    g_offs[N_NODES + 1];
__device__ int    g_cursor[N_NODES];
__device__ int    g_csrc[N_EDGES];
// transposed fp16 weights: layout [n][k], K-major (K=256)
// mats 0-4: W1[i] @ i*65536 ; 5-8: W2a[i] @ (5+i)*65536 ; 9: W2_last (128x256) @ 9*65536
__device__ __half g_wf16[622592];

// ---------------- helpers ----------------
__device__ __forceinline__ uint32_t smem_u32(const void* p) {
    uint32_t a;
    asm("{ .reg .u64 t; cvta.to.shared.u64 t, %1; cvt.u32.u64 %0, t; }" : "=r"(a) : "l"(p));
    return a;
}
__device__ __forceinline__ uint32_t sw128(uint32_t off) { return off ^ ((off >> 3) & 0x70); }

__device__ __forceinline__ void ldm_x4(uint32_t& r0, uint32_t& r1, uint32_t& r2, uint32_t& r3,
                                       uint32_t addr) {
    asm volatile("ldmatrix.sync.aligned.m8n8.x4.shared.b16 {%0,%1,%2,%3}, [%4];"
                 : "=r"(r0), "=r"(r1), "=r"(r2), "=r"(r3) : "r"(addr));
}
__device__ __forceinline__ void mma_f16(float* d, const uint32_t* a, const uint32_t* b) {
    asm volatile(
        "mma.sync.aligned.m16n8k16.row.col.f32.f16.f16.f32 "
        "{%0,%1,%2,%3}, {%4,%5,%6,%7}, {%8,%9}, {%0,%1,%2,%3};"
        : "+f"(d[0]), "+f"(d[1]), "+f"(d[2]), "+f"(d[3])
        : "r"(a[0]), "r"(a[1]), "r"(a[2]), "r"(a[3]), "r"(b[0]), "r"(b[1]));
}

// ---------------- CSR build ----------------
__global__ void count_kernel(const int* __restrict__ dst) {
    int e = blockIdx.x * blockDim.x + threadIdx.x;
    if (e < N_EDGES) atomicAdd(&g_deg[dst[e]], 1);
}

__global__ void scan_kernel() {
    __shared__ int carry;
    __shared__ int wsum[32];
    int tid = threadIdx.x, lane = tid & 31, wid = tid >> 5;
    if (tid == 0) carry = 0;
    __syncthreads();
    for (int base = 0; base < N_NODES; base += 1024) {
        int i = base + tid;
        int v = (i < N_NODES) ? g_deg[i] : 0;
        int s = v;
        #pragma unroll
        for (int d = 1; d < 32; d <<= 1) {
            int t = __shfl_up_sync(0xffffffffu, s, d);
            if (lane >= d) s += t;
        }
        if (lane == 31) wsum[wid] = s;
        __syncthreads();
        if (wid == 0) {
            int ws = wsum[lane];
            #pragma unroll
            for (int d = 1; d < 32; d <<= 1) {
                int t = __shfl_up_sync(0xffffffffu, ws, d);
                if (lane >= d) ws += t;
            }
            wsum[lane] = ws;
        }
        __syncthreads();
        int excl = s - v + (wid > 0 ? wsum[wid - 1] : 0) + carry;
        if (i < N_NODES) { g_offs[i] = excl; g_cursor[i] = excl; }
        int total = wsum[31];
        __syncthreads();
        if (tid == 0) carry += total;
        __syncthreads();
    }
    if (tid == 0) g_offs[N_NODES] = carry;
}

__global__ void fill_kernel(const int* __restrict__ src, const int* __restrict__ dst) {
    int e = blockIdx.x * blockDim.x + threadIdx.x;
    if (e < N_NODES) g_deg[e] = 0;   // re-zero for next kernel_launch call
    if (e < N_EDGES) {
        int d = dst[e];
        int pos = atomicAdd(&g_cursor[d], 1);
        g_csrc[pos] = src[e];
    }
}

// ---------------- weight transpose (fp16) + input pack, one launch ----------------
__global__ void prep_kernel(const float* __restrict__ W1, const float* __restrict__ W2a,
                            const float* __restrict__ W2l, const float* __restrict__ x) {
    int i = blockIdx.x * blockDim.x + threadIdx.x;
    if (i < 622592) {
        const float* src;
        int local, N;
        if (i < 327680)      { src = W1  + (size_t)(i >> 16) * 65536;            local = i & 65535;  N = 256; }
        else if (i < 589824) { src = W2a + (size_t)((i - 327680) >> 16) * 65536; local = (i - 327680) & 65535; N = 256; }
        else                 { src = W2l;                                        local = i - 589824; N = 128; }
        int n = local >> 8, k = local & 255;
        g_wf16[i] = __float2half_rn(src[k * N + n]);
    } else {
        int j = i - 622592;                    // pack x: one per 4 floats
        if (j >= N_NODES * DK / 4) return;
        float4 v = ((const float4*)x)[j];
        __half2 p0 = __float22half2_rn(make_float2(v.x, v.y));
        __half2 p1 = __float22half2_rn(make_float2(v.z, v.w));
        ((uint2*)g_hf16)[j] = make_uint2(*(uint32_t*)&p0, *(uint32_t*)&p1);
    }
}

// ---------------- aggregation: f16 in, fp32 accumulate, output scaled by 1/16 ----------------
__global__ void agg_kernel(const __half* __restrict__ h, __half* __restrict__ z,
                           const float* __restrict__ eps, int layer) {
    int gw = (blockIdx.x * blockDim.x + threadIdx.x) >> 5;
    if (gw >= N_NODES) return;
    int lane = threadIdx.x & 31;
    float e1 = 1.0f + __ldg(&eps[layer]);
    const uint4* h4 = (const uint4*)h;

    uint4 sv = h4[(size_t)gw * 32 + lane];
    float2 a0 = __half22float2(*(__half2*)&sv.x);
    float2 a1 = __half22float2(*(__half2*)&sv.y);
    float2 a2 = __half22float2(*(__half2*)&sv.z);
    float2 a3 = __half22float2(*(__half2*)&sv.w);
    a0.x *= e1; a0.y *= e1; a1.x *= e1; a1.y *= e1;
    a2.x *= e1; a2.y *= e1; a3.x *= e1; a3.y *= e1;

    int beg = g_offs[gw], end = g_offs[gw + 1];
    int j = beg;
    for (; j + 1 < end; j += 2) {
        int u0 = g_csrc[j], u1 = g_csrc[j + 1];
        uint4 b = h4[(size_t)u0 * 32 + lane];
        uint4 c = h4[(size_t)u1 * 32 + lane];
        float2 t;
        t = __half22float2(*(__half2*)&b.x); a0.x += t.x; a0.y += t.y;
        t = __half22float2(*(__half2*)&b.y); a1.x += t.x; a1.y += t.y;
        t = __half22float2(*(__half2*)&b.z); a2.x += t.x; a2.y += t.y;
        t = __half22float2(*(__half2*)&b.w); a3.x += t.x; a3.y += t.y;
        t = __half22float2(*(__half2*)&c.x); a0.x += t.x; a0.y += t.y;
        t = __half22float2(*(__half2*)&c.y); a1.x += t.x; a1.y += t.y;
        t = __half22float2(*(__half2*)&c.z); a2.x += t.x; a2.y += t.y;
        t = __half22float2(*(__half2*)&c.w); a3.x += t.x; a3.y += t.y;
    }
    if (j < end) {
        int u0 = g_csrc[j];
        uint4 b = h4[(size_t)u0 * 32 + lane];
        float2 t;
        t = __half22float2(*(__half2*)&b.x); a0.x += t.x; a0.y += t.y;
        t = __half22float2(*(__half2*)&b.y); a1.x += t.x; a1.y += t.y;
        t = __half22float2(*(__half2*)&b.z); a2.x += t.x; a2.y += t.y;
        t = __half22float2(*(__half2*)&b.w); a3.x += t.x; a3.y += t.y;
    }
    const float S = 0.0625f;   // 1/16 range compression per layer
    a0.x *= S; a0.y *= S; a1.x *= S; a1.y *= S;
    a2.x *= S; a2.y *= S; a3.x *= S; a3.y *= S;
    __half2 o0 = __float22half2_rn(a0), o1 = __float22half2_rn(a1);
    __half2 o2 = __float22half2_rn(a2), o3 = __float22half2_rn(a3);
    ((uint4*)z)[(size_t)gw * 32 + lane] =
        make_uint4(*(uint32_t*)&o0, *(uint32_t*)&o1, *(uint32_t*)&o2, *(uint32_t*)&o3);
}

// ---------------- fp16 HMMA GEMM, tile 128(M)x64(N), single-term ----------------
// NB = row stride of output (256 or 128). Grid: (NB/64, 157).
// EPI 0: stored = relu(acc + bias*rs) -> f16
// EPI 1: stored = relu(acc*g' + ((bias-mean)g'+beta)*rs) -> f16
// EPI 2: out = acc*rs + bias -> f32
template <int NB, int EPI>
__global__ __launch_bounds__(256, 2)
void gemm_hmma(const __half* __restrict__ A, const __half* __restrict__ B,
               float* __restrict__ C, __half* __restrict__ Ch,
               const float* __restrict__ bias,
               const float* __restrict__ bn_g, const float* __restrict__ bn_b,
               const float* __restrict__ bn_m, const float* __restrict__ bn_v,
               float rs) {
    extern __shared__ __align__(1024) char smem[];
    constexpr int OFF_A  = 0;        // 128 x 64 f16 = 16384
    constexpr int OFF_B  = 16384;    // 64 x 64 f16  = 8192
    constexpr int OFF_SC = 24576;    // 64 floats
    constexpr int OFF_SH = 24832;    // 64 floats

    const int tid = threadIdx.x, wid = tid >> 5, lane = tid & 31;
    const int warpM = wid >> 1, warpN = wid & 1;
    const int bm = blockIdx.y * 128, bn = blockIdx.x * 64;
    const uint32_t sb = smem_u32(smem);

    float* SC = (float*)(smem + OFF_SC);
    float* SH = (float*)(smem + OFF_SH);
    if (tid < 64) {
        int n = bn + tid;
        if (EPI == 1) {
            float s = bn_g[n] * rsqrtf(bn_v[n] + BN_EPS);
            SC[tid] = s;
            SH[tid] = ((bias[n] - bn_m[n]) * s + bn_b[n]) * rs;
        } else if (EPI == 0) {
            SC[tid] = 1.0f;
            SH[tid] = bias[n] * rs;
        } else {
            SC[tid] = rs;
            SH[tid] = bias[n];
        }
    }

    float acc[2][4][4];
    #pragma unroll
    for (int f = 0; f < 2; f++)
        #pragma unroll
        for (int j = 0; j < 4; j++)
            #pragma unroll
            for (int q = 0; q < 4; q++) acc[f][j][q] = 0.0f;

    const int mbase = warpM * 32, nwbase = warpN * 32;

    for (int kc = 0; kc < 4; kc++) {
        __syncthreads();
        // stage A chunk: fp16, 128 rows x 64 K-cols, SW128
        #pragma unroll
        for (int it = 0; it < 4; it++) {
            int item = tid + it * 256;
            int r = item >> 3, g = item & 7;
            uint4 v = *(const uint4*)(A + (size_t)(bm + r) * DK + kc * 64 + g * 8);
            *(uint4*)(smem + OFF_A + sw128((uint32_t)(r * 128 + g * 16))) = v;
        }
        // stage B chunk: fp16 [n][k] K-major, 64 rows x 64 K-cols (512 items, 2 per thread)
        #pragma unroll
        for (int it = 0; it < 2; it++) {
            int item = tid + it * 256;
            int n = item >> 3, g = item & 7;
            uint4 v = *(const uint4*)(B + (size_t)(bn + n) * DK + kc * 64 + g * 8);
            *(uint4*)(smem + OFF_B + sw128((uint32_t)(n * 128 + g * 16))) = v;
        }
        __syncthreads();

        #pragma unroll
        for (int kk = 0; kk < 4; kk++) {
            uint32_t a[2][4];
            int arow = mbase + (lane & 15);
            uint32_t akb = kk * 32 + ((lane & 16) ? 16 : 0);
            #pragma unroll
            for (int f = 0; f < 2; f++) {
                uint32_t off = sw128((uint32_t)((arow + f * 16) * 128) + akb);
                ldm_x4(a[f][0], a[f][1], a[f][2], a[f][3], sb + OFF_A + off);
            }
            int brow = nwbase + (lane & 7) + ((lane & 16) ? 8 : 0);
            uint32_t bkb = kk * 32 + ((lane & 8) ? 16 : 0);
            #pragma unroll
            for (int jp = 0; jp < 2; jp++) {
                uint32_t off = sw128((uint32_t)((brow + jp * 16) * 128) + bkb);
                uint32_t bf[4];
                ldm_x4(bf[0], bf[1], bf[2], bf[3], sb + OFF_B + off);
                #pragma unroll
                for (int f = 0; f < 2; f++) {
                    mma_f16(acc[f][2 * jp],     a[f], bf);
                    mma_f16(acc[f][2 * jp + 1], a[f], bf + 2);
                }
            }
        }
    }

    // epilogue
    #pragma unroll
    for (int f = 0; f < 2; f++) {
        int r0 = bm + mbase + f * 16 + (lane >> 2);
        #pragma unroll
        for (int j = 0; j < 4; j++) {
            int nloc = nwbase + j * 8 + (lane & 3) * 2;
            float s0 = SC[nloc], s1 = SC[nloc + 1];
            float t0 = SH[nloc], t1 = SH[nloc + 1];
            float v0 = acc[f][j][0] * s0 + t0;
            float v1 = acc[f][j][1] * s1 + t1;
            float v2 = acc[f][j][2] * s0 + t0;
            float v3 = acc[f][j][3] * s1 + t1;
            if (EPI != 2) {
                v0 = fmaxf(v0, 0.0f); v1 = fmaxf(v1, 0.0f);
                v2 = fmaxf(v2, 0.0f); v3 = fmaxf(v3, 0.0f);
            }
            int col = bn + nloc;
            if (EPI == 2) {
                if (r0 < N_NODES)
                    *(float2*)(C + (size_t)r0 * NB + col) = make_float2(v0, v1);
                if (r0 + 8 < N_NODES)
                    *(float2*)(C + (size_t)(r0 + 8) * NB + col) = make_float2(v2, v3);
            } else {
                __half2 p0 = __float22half2_rn(make_float2(v0, v1));
                __half2 p1 = __float22half2_rn(make_float2(v2, v3));
                if (r0 < N_NODES)
                    *(__half2*)(Ch + (size_t)r0 * NB + col) = p0;
                if (r0 + 8 < N_NODES)
                    *(__half2*)(Ch + (size_t)(r0 + 8) * NB + col) = p1;
            }
        }
    }
}

// ---------------- launch ----------------
extern "C" void kernel_launch(void* const* d_in, const int* in_sizes, int n_in,
                              void* d_out, int out_size) {
    const float* x    = (const float*)d_in[0];
    const int*   ei   = (const int*)d_in[1];
    const float* W1   = (const float*)d_in[2];
    const float* b1   = (const float*)d_in[3];
    const float* W2a  = (const float*)d_in[4];
    const float* b2a  = (const float*)d_in[5];
    const float* W2l  = (const float*)d_in[6];
    const float* b2l  = (const float*)d_in[7];
    const float* eps  = (const float*)d_in[8];
    const float* bng  = (const float*)d_in[9];
    const float* bnb  = (const float*)d_in[10];
    const float* bnm  = (const float*)d_in[11];
    const float* bnv  = (const float*)d_in[12];
    float* out = (float*)d_out;

    void* p;
    cudaGetSymbolAddress(&p, g_zh);   __half* zh = (__half*)p;
    cudaGetSymbolAddress(&p, g_th);   __half* th = (__half*)p;
    cudaGetSymbolAddress(&p, g_hf16); __half* hf = (__half*)p;
    cudaGetSymbolAddress(&p, g_wf16); const __half* wf = (const __half*)p;

    const int* srcp = ei;
    const int* dstp = ei + N_EDGES;

    const int SMEM = 25088 + 256;
    cudaFuncSetAttribute(gemm_hmma<256, 0>, cudaFuncAttributeMaxDynamicSharedMemorySize, SMEM);
    cudaFuncSetAttribute(gemm_hmma<256, 1>, cudaFuncAttributeMaxDynamicSharedMemorySize, SMEM);
    cudaFuncSetAttribute(gemm_hmma<128, 2>, cudaFuncAttributeMaxDynamicSharedMemorySize, SMEM);

    // CSR build (deg re-zeroed by fill; cursor init by scan)
    count_kernel<<<(N_EDGES + 255) / 256, 256>>>(dstp);
    scan_kernel<<<1, 1024>>>();
    fill_kernel<<<(N_EDGES + 255) / 256, 256>>>(srcp, dstp);

    // weight transpose + x pack, one launch
    prep_kernel<<<(622592 + 1280000 + 255) / 256, 256>>>(W1, W2a, W2l, x);

    dim3 g256(4, 157), g128(2, 157);

    // rs for layer i = 16^-(i+1): undoes agg's 1/16 and tracks cumulative scale
    const float RS[5] = {1.0f / 16, 1.0f / 256, 1.0f / 4096, 1.0f / 65536, 1.0f / 1048576};

    for (int i = 0; i < 4; i++) {
        agg_kernel<<<2500, 256>>>(hf, zh, eps, i);
        gemm_hmma<256, 0><<<g256, 256, SMEM>>>(zh, wf + (size_t)i * 65536,
                                               nullptr, th, b1 + i * 256,
                                               nullptr, nullptr, nullptr, nullptr, RS[i]);
        gemm_hmma<256, 1><<<g256, 256, SMEM>>>(th, wf + (size_t)(5 + i) * 65536,
                                               nullptr, hf, b2a + i * 256,
                                               bng + i * 256, bnb + i * 256, bnm + i * 256, bnv + i * 256,
                                               RS[i]);
    }
    agg_kernel<<<2500, 256>>>(hf, zh, eps, 4);
    gemm_hmma<256, 0><<<g256, 256, SMEM>>>(zh, wf + (size_t)4 * 65536,
                                           nullptr, th, b1 + 4 * 256,
                                           nullptr, nullptr, nullptr, nullptr, RS[4]);
    gemm_hmma<128, 2><<<g128, 256, SMEM>>>(th, wf + (size_t)9 * 65536,
                                           out, nullptr, b2l,
                                           nullptr, nullptr, nullptr, nullptr, 1048576.0f);
}